// round 5
// baseline (speedup 1.0000x reference)
#include <cuda_runtime.h>
#include <cuda_bf16.h>
#include <cstdint>

#define GN 2048
#define GD 512
#define GB 8
#define NEG_INF_F (-9999999.0f)

// ---------------- device scratch (no allocs allowed) ----------------
__device__ float          g_scratch[(size_t)GB * GN * GN];  // masked scores S (fp32)
__device__ __nv_bfloat16  g_phi[(size_t)GB * GN * GN];      // softmax probs hi
__device__ __nv_bfloat16  g_plo[(size_t)GB * GN * GN];      // softmax probs lo
__device__ __nv_bfloat16  g_xhi[(size_t)GB * GN * GD];      // X hi   [b,n,d]
__device__ __nv_bfloat16  g_xlo[(size_t)GB * GN * GD];      // X lo   [b,n,d]
__device__ __nv_bfloat16  g_xthi[(size_t)GB * GD * GN];     // X^T hi [b,d,n]
__device__ __nv_bfloat16  g_xtlo[(size_t)GB * GD * GN];     // X^T lo [b,d,n]

// ---------------- helpers ----------------
__device__ __forceinline__ uint32_t smem_u32(const void* p) {
    uint32_t a;
    asm("{ .reg .u64 t; cvta.to.shared.u64 t, %1; cvt.u32.u64 %0, t; }" : "=r"(a) : "l"(p));
    return a;
}

#define CP_ASYNC16(dst, src) \
    asm volatile("cp.async.cg.shared.global [%0], [%1], 16;" :: "r"(dst), "l"(src))
#define CP_COMMIT() asm volatile("cp.async.commit_group;" ::: "memory")
#define CP_WAIT0()  asm volatile("cp.async.wait_group 0;" ::: "memory")

__device__ __forceinline__ void ldsm4(uint32_t* r, uint32_t addr) {
    asm volatile("ldmatrix.sync.aligned.m8n8.x4.shared.b16 {%0,%1,%2,%3}, [%4];"
                 : "=r"(r[0]), "=r"(r[1]), "=r"(r[2]), "=r"(r[3]) : "r"(addr));
}

__device__ __forceinline__ void mma16816(float* c, const uint32_t* a, const uint32_t* b) {
    asm volatile(
        "mma.sync.aligned.m16n8k16.row.col.f32.bf16.bf16.f32 "
        "{%0,%1,%2,%3}, {%4,%5,%6,%7}, {%8,%9}, {%0,%1,%2,%3};"
        : "+f"(c[0]), "+f"(c[1]), "+f"(c[2]), "+f"(c[3])
        : "r"(a[0]), "r"(a[1]), "r"(a[2]), "r"(a[3]), "r"(b[0]), "r"(b[1]));
}

// ---------------- smem layout ----------------
// Per stream tile: 128 rows x 32 bf16, row stride 40 elems (80B) -> conflict-free ldmatrix.
#define ROW_B    80
#define STREAM_B (128 * ROW_B)        // 10240 B
#define STAGE_B  (4 * STREAM_B)       // Ahi, Alo, Bhi, Blo = 40960 B
#define NSTAGE   2
#define SMEM_BYTES (NSTAGE * STAGE_B) // 81920 B  -> 2 CTAs / SM

// Load one 4-stream stage (k-chunk of 32) with cp.async. 256 threads.
__device__ __forceinline__ void load_stage(uint32_t smemStage,
                                           const __nv_bfloat16* a_hi,
                                           const __nv_bfloat16* a_lo, int ldA,
                                           const __nv_bfloat16* b_hi,
                                           const __nv_bfloat16* b_lo, int ldB,
                                           int k0) {
    const int t = threadIdx.x;
    const __nv_bfloat16* srcs[4] = {a_hi, a_lo, b_hi, b_lo};
    const int lds[4] = {ldA, ldA, ldB, ldB};
#pragma unroll
    for (int st = 0; st < 4; st++) {
#pragma unroll
        for (int rep = 0; rep < 2; rep++) {
            int c   = t + rep * 256;          // 0..511
            int row = c >> 2;                 // 0..127
            int k8  = c & 3;                  // 16B chunk within 32-elem row
            uint32_t d = smemStage + st * STREAM_B + row * ROW_B + k8 * 16;
            const __nv_bfloat16* s = srcs[st] + (size_t)row * lds[st] + k0 + k8 * 8;
            CP_ASYNC16(d, s);
        }
    }
}

// Core: acc[2][8][4] += A(128 x K) * B(128 x K)^T with bf16 hi/lo 3-term split.
// Warp layout: 4 (m) x 2 (n); warp tile 32 x 64. Double-buffered cp.async,
// ONE __syncthreads per k-iter:
//   wait0 -> sync (stage i ready; all reads of buf[(i+1)&1] finished in i-1)
//   -> prefetch stage i+1 -> compute stage i.
__device__ __forceinline__ void gemm_core(uint32_t sb,
                                          const __nv_bfloat16* a_hi,
                                          const __nv_bfloat16* a_lo, int ldA,
                                          const __nv_bfloat16* b_hi,
                                          const __nv_bfloat16* b_lo, int ldB,
                                          int ksteps, float acc[2][8][4]) {
    const int l = threadIdx.x & 31;
    const int w = threadIdx.x >> 5;
    const int wm = (w & 3) * 32;
    const int wn = (w >> 2) * 64;

    // ldmatrix lane address components
    const int aRow = wm + (l & 15);
    const int aCb  = (l >> 4) * 16;
    const int bRow = wn + (l & 7) + ((l >> 4) & 1) * 8;
    const int bCb  = ((l >> 3) & 1) * 16;

    // prologue: stage 0
    load_stage(sb, a_hi, a_lo, ldA, b_hi, b_lo, ldB, 0);
    CP_COMMIT();

#pragma unroll 1
    for (int i = 0; i < ksteps; i++) {
        CP_WAIT0();            // only stage i in flight -> it is complete
        __syncthreads();       // publish stage i; prove buf[(i+1)&1] reads done

        if (i + 1 < ksteps) {  // prefetch overlaps compute below
            load_stage(sb + ((i + 1) & 1) * STAGE_B,
                       a_hi, a_lo, ldA, b_hi, b_lo, ldB, (i + 1) * 32);
            CP_COMMIT();
        }

        const uint32_t stg = sb + (i & 1) * STAGE_B;
#pragma unroll
        for (int s = 0; s < 2; s++) {
            uint32_t ah[2][4], al[2][4];
#pragma unroll
            for (int mf = 0; mf < 2; mf++) {
                uint32_t ad = stg + (aRow + mf * 16) * ROW_B + s * 32 + aCb;
                ldsm4(ah[mf], ad);
                ldsm4(al[mf], ad + STREAM_B);
            }
            uint32_t bh[4][4], bl[4][4];
#pragma unroll
            for (int nq = 0; nq < 4; nq++) {
                uint32_t bd = stg + 2 * STREAM_B + (bRow + nq * 16) * ROW_B + s * 32 + bCb;
                ldsm4(bh[nq], bd);
                ldsm4(bl[nq], bd + STREAM_B);
            }
            // 3 passes -> no back-to-back RAW on the same accumulator
#pragma unroll
            for (int mf = 0; mf < 2; mf++)
#pragma unroll
                for (int nq = 0; nq < 4; nq++)
#pragma unroll
                    for (int h = 0; h < 2; h++)
                        mma16816(acc[mf][nq * 2 + h], ah[mf], &bh[nq][h * 2]); // hi*hi
#pragma unroll
            for (int mf = 0; mf < 2; mf++)
#pragma unroll
                for (int nq = 0; nq < 4; nq++)
#pragma unroll
                    for (int h = 0; h < 2; h++)
                        mma16816(acc[mf][nq * 2 + h], ah[mf], &bl[nq][h * 2]); // hi*lo
#pragma unroll
            for (int mf = 0; mf < 2; mf++)
#pragma unroll
                for (int nq = 0; nq < 4; nq++)
#pragma unroll
                    for (int h = 0; h < 2; h++)
                        mma16816(acc[mf][nq * 2 + h], al[mf], &bh[nq][h * 2]); // lo*hi
        }
    }
}

// ---------------------------------------------------------------------------
// Kernel 0: split X into bf16 hi/lo, plus transposed copies.
// ---------------------------------------------------------------------------
__global__ __launch_bounds__(256) void convert_split(const float* __restrict__ X) {
    __shared__ float tile[32][33];
    const int b  = blockIdx.z;
    const int d0 = blockIdx.x * 32;
    const int n0 = blockIdx.y * 32;
    const int tx = threadIdx.x & 31;
    const int ty = threadIdx.x >> 5;
    const float* Xb = X + (size_t)b * GN * GD;

#pragma unroll
    for (int k = 0; k < 4; k++) {
        int n = n0 + ty + k * 8;
        float v = Xb[(size_t)n * GD + d0 + tx];
        tile[ty + k * 8][tx] = v;
        __nv_bfloat16 h = __float2bfloat16(v);
        float lo = v - __bfloat162float(h);
        size_t idx = ((size_t)b * GN + n) * GD + d0 + tx;
        g_xhi[idx] = h;
        g_xlo[idx] = __float2bfloat16(lo);
    }
    __syncthreads();
#pragma unroll
    for (int k = 0; k < 4; k++) {
        int d = d0 + ty + k * 8;
        float v = tile[tx][ty + k * 8];
        __nv_bfloat16 h = __float2bfloat16(v);
        float lo = v - __bfloat162float(h);
        size_t idx = ((size_t)b * GD + d) * GN + n0 + tx;
        g_xthi[idx] = h;
        g_xtlo[idx] = __float2bfloat16(lo);
    }
}

// ---------------------------------------------------------------------------
// Kernel 1: S = X X^T masked by adj (+self) -> g_scratch (fp32).
// ---------------------------------------------------------------------------
__global__ __launch_bounds__(256, 2) void gemm1_mma(const int* __restrict__ adj) {
    extern __shared__ char smem[];
    const uint32_t sb = smem_u32(smem);
    const int b = blockIdx.z;
    const int rowBase = blockIdx.y * 128;
    const int colBase = blockIdx.x * 128;

    float acc[2][8][4] = {};
    gemm_core(sb,
              g_xhi + ((size_t)b * GN + rowBase) * GD,
              g_xlo + ((size_t)b * GN + rowBase) * GD, GD,
              g_xhi + ((size_t)b * GN + colBase) * GD,
              g_xlo + ((size_t)b * GN + colBase) * GD, GD,
              GD / 32, acc);

    const int l = threadIdx.x & 31;
    const int w = threadIdx.x >> 5;
    const int wm = (w & 3) * 32;
    const int wn = (w >> 2) * 64;
    const int* adjb = adj + (size_t)b * GN * GN;
    float* Sb = g_scratch + (size_t)b * GN * GN;

#pragma unroll
    for (int mf = 0; mf < 2; mf++) {
        const int r0 = rowBase + wm + mf * 16 + (l >> 2);
        const int r1 = r0 + 8;
#pragma unroll
        for (int nf = 0; nf < 8; nf++) {
            const int c = colBase + wn + nf * 8 + (l & 3) * 2;
            int2 a0 = *(const int2*)(adjb + (size_t)r0 * GN + c);
            int2 a1 = *(const int2*)(adjb + (size_t)r1 * GN + c);
            float2 o0, o1;
            o0.x = (a0.x != 0 || r0 == c)     ? acc[mf][nf][0] : NEG_INF_F;
            o0.y = (a0.y != 0 || r0 == c + 1) ? acc[mf][nf][1] : NEG_INF_F;
            o1.x = (a1.x != 0 || r1 == c)     ? acc[mf][nf][2] : NEG_INF_F;
            o1.y = (a1.y != 0 || r1 == c + 1) ? acc[mf][nf][3] : NEG_INF_F;
            *(float2*)(Sb + (size_t)r0 * GN + c) = o0;
            *(float2*)(Sb + (size_t)r1 * GN + c) = o1;
        }
    }
}

// ---------------------------------------------------------------------------
// Kernel 2: row softmax over g_scratch -> bf16 hi/lo probs.
// ---------------------------------------------------------------------------
__device__ __forceinline__ float warpMax(float v) {
#pragma unroll
    for (int o = 16; o > 0; o >>= 1) v = fmaxf(v, __shfl_xor_sync(0xffffffffu, v, o));
    return v;
}
__device__ __forceinline__ float warpSum(float v) {
#pragma unroll
    for (int o = 16; o > 0; o >>= 1) v += __shfl_xor_sync(0xffffffffu, v, o);
    return v;
}
__device__ __forceinline__ void store_split4(__nv_bfloat16* ph, __nv_bfloat16* pl,
                                             int e4, float4 v) {
    __nv_bfloat16 h0 = __float2bfloat16(v.x), h1 = __float2bfloat16(v.y);
    __nv_bfloat16 h2 = __float2bfloat16(v.z), h3 = __float2bfloat16(v.w);
    __nv_bfloat162 H0; H0.x = h0; H0.y = h1;
    __nv_bfloat162 H1; H1.x = h2; H1.y = h3;
    __nv_bfloat162 L0, L1;
    L0.x = __float2bfloat16(v.x - __bfloat162float(h0));
    L0.y = __float2bfloat16(v.y - __bfloat162float(h1));
    L1.x = __float2bfloat16(v.z - __bfloat162float(h2));
    L1.y = __float2bfloat16(v.w - __bfloat162float(h3));
    ((__nv_bfloat162*)ph)[e4 * 2]     = H0;
    ((__nv_bfloat162*)ph)[e4 * 2 + 1] = H1;
    ((__nv_bfloat162*)pl)[e4 * 2]     = L0;
    ((__nv_bfloat162*)pl)[e4 * 2 + 1] = L1;
}

__global__ __launch_bounds__(256) void softmax_split() {
    __shared__ float red[8];
    const size_t row = blockIdx.x;
    const float* p = g_scratch + row * GN;
    const int tid = threadIdx.x;

    float4 v0 = ((const float4*)p)[tid];
    float4 v1 = ((const float4*)p)[tid + 256];

    float m = fmaxf(fmaxf(fmaxf(v0.x, v0.y), fmaxf(v0.z, v0.w)),
                    fmaxf(fmaxf(v1.x, v1.y), fmaxf(v1.z, v1.w)));
    m = warpMax(m);
    if ((tid & 31) == 0) red[tid >> 5] = m;
    __syncthreads();
    m = red[0];
#pragma unroll
    for (int i = 1; i < 8; i++) m = fmaxf(m, red[i]);
    __syncthreads();

    v0.x = expf(v0.x - m); v0.y = expf(v0.y - m);
    v0.z = expf(v0.z - m); v0.w = expf(v0.w - m);
    v1.x = expf(v1.x - m); v1.y = expf(v1.y - m);
    v1.z = expf(v1.z - m); v1.w = expf(v1.w - m);

    float s = (v0.x + v0.y + v0.z + v0.w) + (v1.x + v1.y + v1.z + v1.w);
    s = warpSum(s);
    if ((tid & 31) == 0) red[tid >> 5] = s;
    __syncthreads();
    s = red[0] + red[1] + red[2] + red[3] + red[4] + red[5] + red[6] + red[7];

    const float inv = 1.0f / s;
    v0.x *= inv; v0.y *= inv; v0.z *= inv; v0.w *= inv;
    v1.x *= inv; v1.y *= inv; v1.z *= inv; v1.w *= inv;

    __nv_bfloat16* ph = g_phi + row * GN;
    __nv_bfloat16* pl = g_plo + row * GN;
    store_split4(ph, pl, tid, v0);
    store_split4(ph, pl, tid + 256, v1);
}

// ---------------------------------------------------------------------------
// Kernel 3: O = P X. A = P (k = m contiguous), B = X^T (k = m contiguous).
// ---------------------------------------------------------------------------
__global__ __launch_bounds__(256, 2) void gemm2_mma(float* __restrict__ out) {
    extern __shared__ char smem[];
    const uint32_t sb = smem_u32(smem);
    const int b = blockIdx.z;
    const int rowBase = blockIdx.y * 128;   // n
    const int colBase = blockIdx.x * 128;   // d

    float acc[2][8][4] = {};
    gemm_core(sb,
              g_phi  + ((size_t)b * GN + rowBase) * GN,
              g_plo  + ((size_t)b * GN + rowBase) * GN, GN,
              g_xthi + ((size_t)b * GD + colBase) * GN,
              g_xtlo + ((size_t)b * GD + colBase) * GN, GN,
              GN / 32, acc);

    const int l = threadIdx.x & 31;
    const int w = threadIdx.x >> 5;
    const int wm = (w & 3) * 32;
    const int wn = (w >> 2) * 64;
    float* Ob = out + (size_t)b * GN * GD;

#pragma unroll
    for (int mf = 0; mf < 2; mf++) {
        const int r0 = rowBase + wm + mf * 16 + (l >> 2);
        const int r1 = r0 + 8;
#pragma unroll
        for (int nf = 0; nf < 8; nf++) {
            const int c = colBase + wn + nf * 8 + (l & 3) * 2;
            *(float2*)(Ob + (size_t)r0 * GD + c) =
                make_float2(acc[mf][nf][0], acc[mf][nf][1]);
            *(float2*)(Ob + (size_t)r1 * GD + c) =
                make_float2(acc[mf][nf][2], acc[mf][nf][3]);
        }
    }
}

// ---------------------------------------------------------------------------
extern "C" void kernel_launch(void* const* d_in, const int* in_sizes, int n_in,
                              void* d_out, int out_size) {
    const float* X   = (const float*)d_in[0];
    const int*   adj = (const int*)d_in[2];
    float*       out = (float*)d_out;

    static bool attrDone = false;
    if (!attrDone) {
        cudaFuncSetAttribute(gemm1_mma, cudaFuncAttributeMaxDynamicSharedMemorySize, SMEM_BYTES);
        cudaFuncSetAttribute(gemm2_mma, cudaFuncAttributeMaxDynamicSharedMemorySize, SMEM_BYTES);
        attrDone = true;
    }

    convert_split<<<dim3(GD / 32, GN / 32, GB), 256>>>(X);
    gemm1_mma<<<dim3(GN / 128, GN / 128, GB), 256, SMEM_BYTES>>>(adj);
    softmax_split<<<GB * GN, 256>>>();
    gemm2_mma<<<dim3(GD / 128, GN / 128, GB), 256, SMEM_BYTES>>>(out);
}

// round 6
// speedup vs baseline: 1.1964x; 1.1964x over previous
#include <cuda_runtime.h>
#include <cuda_bf16.h>
#include <cstdint>

#define GN 2048
#define GD 512
#define GB 8
#define NEG_INF_F (-9999999.0f)

// ---------------- device scratch (no allocs allowed) ----------------
__device__ float          g_scratch[(size_t)GB * GN * GN];  // masked scores S (fp32)
__device__ __nv_bfloat16  g_phi[(size_t)GB * GN * GN];      // softmax probs hi
__device__ __nv_bfloat16  g_plo[(size_t)GB * GN * GN];      // softmax probs lo
__device__ __nv_bfloat16  g_xhi[(size_t)GB * GN * GD];      // X hi   [b,n,d]
__device__ __nv_bfloat16  g_xlo[(size_t)GB * GN * GD];      // X lo   [b,n,d]
__device__ __nv_bfloat16  g_xthi[(size_t)GB * GD * GN];     // X^T hi [b,d,n]
__device__ __nv_bfloat16  g_xtlo[(size_t)GB * GD * GN];     // X^T lo [b,d,n]

// ---------------- helpers ----------------
__device__ __forceinline__ uint32_t smem_u32(const void* p) {
    uint32_t a;
    asm("{ .reg .u64 t; cvta.to.shared.u64 t, %1; cvt.u32.u64 %0, t; }" : "=r"(a) : "l"(p));
    return a;
}

#define CP_ASYNC16(dst, src) \
    asm volatile("cp.async.cg.shared.global [%0], [%1], 16;" :: "r"(dst), "l"(src))
#define CP_COMMIT() asm volatile("cp.async.commit_group;" ::: "memory")
#define CP_WAIT0()  asm volatile("cp.async.wait_group 0;" ::: "memory")

__device__ __forceinline__ void ldsm4(uint32_t* r, uint32_t addr) {
    asm volatile("ldmatrix.sync.aligned.m8n8.x4.shared.b16 {%0,%1,%2,%3}, [%4];"
                 : "=r"(r[0]), "=r"(r[1]), "=r"(r[2]), "=r"(r[3]) : "r"(addr));
}

__device__ __forceinline__ void mma16816(float* c, const uint32_t* a, const uint32_t* b) {
    asm volatile(
        "mma.sync.aligned.m16n8k16.row.col.f32.bf16.bf16.f32 "
        "{%0,%1,%2,%3}, {%4,%5,%6,%7}, {%8,%9}, {%0,%1,%2,%3};"
        : "+f"(c[0]), "+f"(c[1]), "+f"(c[2]), "+f"(c[3])
        : "r"(a[0]), "r"(a[1]), "r"(a[2]), "r"(a[3]), "r"(b[0]), "r"(b[1]));
}

// ---------------- smem layout ----------------
// Per stream tile: 128 rows x 32 bf16, row stride 40 elems (80B) -> conflict-free ldmatrix.
#define ROW_B    80
#define STREAM_B (128 * ROW_B)        // 10240 B
#define STAGE_B  (4 * STREAM_B)       // Ahi, Alo, Bhi, Blo = 40960 B
#define NSTAGE   2
#define SMEM_BYTES (NSTAGE * STAGE_B) // 81920 B  -> 2 CTAs / SM

// Load one 4-stream stage (k-chunk of 32) with cp.async. 256 threads.
__device__ __forceinline__ void load_stage(uint32_t smemStage,
                                           const __nv_bfloat16* a_hi,
                                           const __nv_bfloat16* a_lo, int ldA,
                                           const __nv_bfloat16* b_hi,
                                           const __nv_bfloat16* b_lo, int ldB,
                                           int k0) {
    const int t = threadIdx.x;
    const __nv_bfloat16* srcs[4] = {a_hi, a_lo, b_hi, b_lo};
    const int lds[4] = {ldA, ldA, ldB, ldB};
#pragma unroll
    for (int st = 0; st < 4; st++) {
#pragma unroll
        for (int rep = 0; rep < 2; rep++) {
            int c   = t + rep * 256;          // 0..511
            int row = c >> 2;                 // 0..127
            int k8  = c & 3;                  // 16B chunk within 32-elem row
            uint32_t d = smemStage + st * STREAM_B + row * ROW_B + k8 * 16;
            const __nv_bfloat16* s = srcs[st] + (size_t)row * lds[st] + k0 + k8 * 8;
            CP_ASYNC16(d, s);
        }
    }
}

// Core: acc[2][8][4] += A(128 x K) * B(128 x K)^T with bf16 hi/lo 3-term split.
// Warp layout: 4 (m) x 2 (n); warp tile 32 x 64. Double-buffered cp.async,
// one __syncthreads per k-iter.
__device__ __forceinline__ void gemm_core(uint32_t sb,
                                          const __nv_bfloat16* a_hi,
                                          const __nv_bfloat16* a_lo, int ldA,
                                          const __nv_bfloat16* b_hi,
                                          const __nv_bfloat16* b_lo, int ldB,
                                          int ksteps, float acc[2][8][4]) {
    const int l = threadIdx.x & 31;
    const int w = threadIdx.x >> 5;
    const int wm = (w & 3) * 32;
    const int wn = (w >> 2) * 64;

    const int aRow = wm + (l & 15);
    const int aCb  = (l >> 4) * 16;
    const int bRow = wn + (l & 7) + ((l >> 4) & 1) * 8;
    const int bCb  = ((l >> 3) & 1) * 16;

    load_stage(sb, a_hi, a_lo, ldA, b_hi, b_lo, ldB, 0);
    CP_COMMIT();

#pragma unroll 1
    for (int i = 0; i < ksteps; i++) {
        CP_WAIT0();
        __syncthreads();

        if (i + 1 < ksteps) {
            load_stage(sb + ((i + 1) & 1) * STAGE_B,
                       a_hi, a_lo, ldA, b_hi, b_lo, ldB, (i + 1) * 32);
            CP_COMMIT();
        }

        const uint32_t stg = sb + (i & 1) * STAGE_B;
#pragma unroll
        for (int s = 0; s < 2; s++) {
            uint32_t ah[2][4], al[2][4];
#pragma unroll
            for (int mf = 0; mf < 2; mf++) {
                uint32_t ad = stg + (aRow + mf * 16) * ROW_B + s * 32 + aCb;
                ldsm4(ah[mf], ad);
                ldsm4(al[mf], ad + STREAM_B);
            }
            uint32_t bh[4][4], bl[4][4];
#pragma unroll
            for (int nq = 0; nq < 4; nq++) {
                uint32_t bd = stg + 2 * STREAM_B + (bRow + nq * 16) * ROW_B + s * 32 + bCb;
                ldsm4(bh[nq], bd);
                ldsm4(bl[nq], bd + STREAM_B);
            }
#pragma unroll
            for (int mf = 0; mf < 2; mf++)
#pragma unroll
                for (int nq = 0; nq < 4; nq++)
#pragma unroll
                    for (int h = 0; h < 2; h++)
                        mma16816(acc[mf][nq * 2 + h], ah[mf], &bh[nq][h * 2]); // hi*hi
#pragma unroll
            for (int mf = 0; mf < 2; mf++)
#pragma unroll
                for (int nq = 0; nq < 4; nq++)
#pragma unroll
                    for (int h = 0; h < 2; h++)
                        mma16816(acc[mf][nq * 2 + h], ah[mf], &bl[nq][h * 2]); // hi*lo
#pragma unroll
            for (int mf = 0; mf < 2; mf++)
#pragma unroll
                for (int nq = 0; nq < 4; nq++)
#pragma unroll
                    for (int h = 0; h < 2; h++)
                        mma16816(acc[mf][nq * 2 + h], al[mf], &bh[nq][h * 2]); // lo*hi
        }
    }
}

// ---------------------------------------------------------------------------
// Kernel 0: split X into bf16 hi/lo, plus transposed copies.
// ---------------------------------------------------------------------------
__global__ __launch_bounds__(256) void convert_split(const float* __restrict__ X) {
    __shared__ float tile[32][33];
    const int b  = blockIdx.z;
    const int d0 = blockIdx.x * 32;
    const int n0 = blockIdx.y * 32;
    const int tx = threadIdx.x & 31;
    const int ty = threadIdx.x >> 5;
    const float* Xb = X + (size_t)b * GN * GD;

#pragma unroll
    for (int k = 0; k < 4; k++) {
        int n = n0 + ty + k * 8;
        float v = Xb[(size_t)n * GD + d0 + tx];
        tile[ty + k * 8][tx] = v;
        __nv_bfloat16 h = __float2bfloat16(v);
        float lo = v - __bfloat162float(h);
        size_t idx = ((size_t)b * GN + n) * GD + d0 + tx;
        g_xhi[idx] = h;
        g_xlo[idx] = __float2bfloat16(lo);
    }
    __syncthreads();
#pragma unroll
    for (int k = 0; k < 4; k++) {
        int d = d0 + ty + k * 8;
        float v = tile[tx][ty + k * 8];
        __nv_bfloat16 h = __float2bfloat16(v);
        float lo = v - __bfloat162float(h);
        size_t idx = ((size_t)b * GD + d) * GN + n0 + tx;
        g_xthi[idx] = h;
        g_xtlo[idx] = __float2bfloat16(lo);
    }
}

// ---------------------------------------------------------------------------
// Kernel 1: S = X X^T masked by adj (+self) -> g_scratch (fp32).
// SYMMETRIC: compute only upper-triangular tile pairs (R <= C), write both
// (R,C) and its transpose (C,R) with their own adjacency masks.
// ---------------------------------------------------------------------------
__global__ __launch_bounds__(256, 2) void gemm1_mma(const int* __restrict__ adj) {
    extern __shared__ char smem[];
    const uint32_t sb = smem_u32(smem);
    const int b = blockIdx.z;

    // decode triangular pair index -> (R, C) with C >= R, 16x16 tile grid
    int rem = blockIdx.x;
    int R = 0;
    while (rem >= 16 - R) { rem -= 16 - R; R++; }
    const int C = R + rem;
    const int rowBase = R * 128;
    const int colBase = C * 128;

    float acc[2][8][4] = {};
    gemm_core(sb,
              g_xhi + ((size_t)b * GN + rowBase) * GD,
              g_xlo + ((size_t)b * GN + rowBase) * GD, GD,
              g_xhi + ((size_t)b * GN + colBase) * GD,
              g_xlo + ((size_t)b * GN + colBase) * GD, GD,
              GD / 32, acc);

    const int l = threadIdx.x & 31;
    const int w = threadIdx.x >> 5;
    const int wm = (w & 3) * 32;
    const int wn = (w >> 2) * 64;
    const int* adjb = adj + (size_t)b * GN * GN;
    float* Sb = g_scratch + (size_t)b * GN * GN;

    // ---- write block (R, C): S[n][m] = acc, mask adj[n][m] ----
#pragma unroll
    for (int mf = 0; mf < 2; mf++) {
        const int r0 = rowBase + wm + mf * 16 + (l >> 2);
        const int r1 = r0 + 8;
#pragma unroll
        for (int nf = 0; nf < 8; nf++) {
            const int c = colBase + wn + nf * 8 + (l & 3) * 2;
            int2 a0 = *(const int2*)(adjb + (size_t)r0 * GN + c);
            int2 a1 = *(const int2*)(adjb + (size_t)r1 * GN + c);
            float2 o0, o1;
            o0.x = (a0.x != 0 || r0 == c)     ? acc[mf][nf][0] : NEG_INF_F;
            o0.y = (a0.y != 0 || r0 == c + 1) ? acc[mf][nf][1] : NEG_INF_F;
            o1.x = (a1.x != 0 || r1 == c)     ? acc[mf][nf][2] : NEG_INF_F;
            o1.y = (a1.y != 0 || r1 == c + 1) ? acc[mf][nf][3] : NEG_INF_F;
            *(float2*)(Sb + (size_t)r0 * GN + c) = o0;
            *(float2*)(Sb + (size_t)r1 * GN + c) = o1;
        }
    }

    // ---- mirror block (C, R): S[m][n] = acc^T, mask adj[m][n] ----
    if (C != R) {
        __syncthreads();                     // mainloop smem reads complete
        float* T = (float*)smem;             // [128][132] fp32 transpose stage
        // store: T[m_local][n_local] = acc(n_local, m_local)
#pragma unroll
        for (int mf = 0; mf < 2; mf++) {
            const int rl0 = wm + mf * 16 + (l >> 2);   // n_local
            const int rl1 = rl0 + 8;
#pragma unroll
            for (int nf = 0; nf < 8; nf++) {
                const int cl = wn + nf * 8 + (l & 3) * 2;   // m_local
                T[(cl)     * 132 + rl0] = acc[mf][nf][0];
                T[(cl + 1) * 132 + rl0] = acc[mf][nf][1];
                T[(cl)     * 132 + rl1] = acc[mf][nf][2];
                T[(cl + 1) * 132 + rl1] = acc[mf][nf][3];
            }
        }
        __syncthreads();
        // read rows of T coalesced, write mirror block with adj[m][n] mask.
        // (m and n ranges are disjoint here, so no self-loop check needed.)
#pragma unroll
        for (int mf = 0; mf < 2; mf++) {
            const int ml0 = wm + mf * 16 + (l >> 2);   // m_local
            const int ml1 = ml0 + 8;
            const int m0 = colBase + ml0;
            const int m1 = colBase + ml1;
#pragma unroll
            for (int nf = 0; nf < 8; nf++) {
                const int nl = wn + nf * 8 + (l & 3) * 2;   // n_local
                const int nn = rowBase + nl;
                float2 v0 = make_float2(T[ml0 * 132 + nl], T[ml0 * 132 + nl + 1]);
                float2 v1 = make_float2(T[ml1 * 132 + nl], T[ml1 * 132 + nl + 1]);
                int2 a0 = *(const int2*)(adjb + (size_t)m0 * GN + nn);
                int2 a1 = *(const int2*)(adjb + (size_t)m1 * GN + nn);
                float2 o0, o1;
                o0.x = (a0.x != 0) ? v0.x : NEG_INF_F;
                o0.y = (a0.y != 0) ? v0.y : NEG_INF_F;
                o1.x = (a1.x != 0) ? v1.x : NEG_INF_F;
                o1.y = (a1.y != 0) ? v1.y : NEG_INF_F;
                *(float2*)(Sb + (size_t)m0 * GN + nn) = o0;
                *(float2*)(Sb + (size_t)m1 * GN + nn) = o1;
            }
        }
    }
}

// ---------------------------------------------------------------------------
// Kernel 2: row softmax over g_scratch -> bf16 hi/lo probs.
// ---------------------------------------------------------------------------
__device__ __forceinline__ float warpMax(float v) {
#pragma unroll
    for (int o = 16; o > 0; o >>= 1) v = fmaxf(v, __shfl_xor_sync(0xffffffffu, v, o));
    return v;
}
__device__ __forceinline__ float warpSum(float v) {
#pragma unroll
    for (int o = 16; o > 0; o >>= 1) v += __shfl_xor_sync(0xffffffffu, v, o);
    return v;
}
__device__ __forceinline__ void store_split4(__nv_bfloat16* ph, __nv_bfloat16* pl,
                                             int e4, float4 v) {
    __nv_bfloat16 h0 = __float2bfloat16(v.x), h1 = __float2bfloat16(v.y);
    __nv_bfloat16 h2 = __float2bfloat16(v.z), h3 = __float2bfloat16(v.w);
    __nv_bfloat162 H0; H0.x = h0; H0.y = h1;
    __nv_bfloat162 H1; H1.x = h2; H1.y = h3;
    __nv_bfloat162 L0, L1;
    L0.x = __float2bfloat16(v.x - __bfloat162float(h0));
    L0.y = __float2bfloat16(v.y - __bfloat162float(h1));
    L1.x = __float2bfloat16(v.z - __bfloat162float(h2));
    L1.y = __float2bfloat16(v.w - __bfloat162float(h3));
    ((__nv_bfloat162*)ph)[e4 * 2]     = H0;
    ((__nv_bfloat162*)ph)[e4 * 2 + 1] = H1;
    ((__nv_bfloat162*)pl)[e4 * 2]     = L0;
    ((__nv_bfloat162*)pl)[e4 * 2 + 1] = L1;
}

__global__ __launch_bounds__(256) void softmax_split() {
    __shared__ float red[8];
    const size_t row = blockIdx.x;
    const float* p = g_scratch + row * GN;
    const int tid = threadIdx.x;

    float4 v0 = ((const float4*)p)[tid];
    float4 v1 = ((const float4*)p)[tid + 256];

    float m = fmaxf(fmaxf(fmaxf(v0.x, v0.y), fmaxf(v0.z, v0.w)),
                    fmaxf(fmaxf(v1.x, v1.y), fmaxf(v1.z, v1.w)));
    m = warpMax(m);
    if ((tid & 31) == 0) red[tid >> 5] = m;
    __syncthreads();
    m = red[0];
#pragma unroll
    for (int i = 1; i < 8; i++) m = fmaxf(m, red[i]);
    __syncthreads();

    v0.x = expf(v0.x - m); v0.y = expf(v0.y - m);
    v0.z = expf(v0.z - m); v0.w = expf(v0.w - m);
    v1.x = expf(v1.x - m); v1.y = expf(v1.y - m);
    v1.z = expf(v1.z - m); v1.w = expf(v1.w - m);

    float s = (v0.x + v0.y + v0.z + v0.w) + (v1.x + v1.y + v1.z + v1.w);
    s = warpSum(s);
    if ((tid & 31) == 0) red[tid >> 5] = s;
    __syncthreads();
    s = red[0] + red[1] + red[2] + red[3] + red[4] + red[5] + red[6] + red[7];

    const float inv = 1.0f / s;
    v0.x *= inv; v0.y *= inv; v0.z *= inv; v0.w *= inv;
    v1.x *= inv; v1.y *= inv; v1.z *= inv; v1.w *= inv;

    __nv_bfloat16* ph = g_phi + row * GN;
    __nv_bfloat16* pl = g_plo + row * GN;
    store_split4(ph, pl, tid, v0);
    store_split4(ph, pl, tid + 256, v1);
}

// ---------------------------------------------------------------------------
// Kernel 3: O = P X. A = P (k = m contiguous), B = X^T (k = m contiguous).
// ---------------------------------------------------------------------------
__global__ __launch_bounds__(256, 2) void gemm2_mma(float* __restrict__ out) {
    extern __shared__ char smem[];
    const uint32_t sb = smem_u32(smem);
    const int b = blockIdx.z;
    const int rowBase = blockIdx.y * 128;   // n
    const int colBase = blockIdx.x * 128;   // d

    float acc[2][8][4] = {};
    gemm_core(sb,
              g_phi  + ((size_t)b * GN + rowBase) * GN,
              g_plo  + ((size_t)b * GN + rowBase) * GN, GN,
              g_xthi + ((size_t)b * GD + colBase) * GN,
              g_xtlo + ((size_t)b * GD + colBase) * GN, GN,
              GN / 32, acc);

    const int l = threadIdx.x & 31;
    const int w = threadIdx.x >> 5;
    const int wm = (w & 3) * 32;
    const int wn = (w >> 2) * 64;
    float* Ob = out + (size_t)b * GN * GD;

#pragma unroll
    for (int mf = 0; mf < 2; mf++) {
        const int r0 = rowBase + wm + mf * 16 + (l >> 2);
        const int r1 = r0 + 8;
#pragma unroll
        for (int nf = 0; nf < 8; nf++) {
            const int c = colBase + wn + nf * 8 + (l & 3) * 2;
            *(float2*)(Ob + (size_t)r0 * GD + c) =
                make_float2(acc[mf][nf][0], acc[mf][nf][1]);
            *(float2*)(Ob + (size_t)r1 * GD + c) =
                make_float2(acc[mf][nf][2], acc[mf][nf][3]);
        }
    }
}

// ---------------------------------------------------------------------------
extern "C" void kernel_launch(void* const* d_in, const int* in_sizes, int n_in,
                              void* d_out, int out_size) {
    const float* X   = (const float*)d_in[0];
    const int*   adj = (const int*)d_in[2];
    float*       out = (float*)d_out;

    static bool attrDone = false;
    if (!attrDone) {
        cudaFuncSetAttribute(gemm1_mma, cudaFuncAttributeMaxDynamicSharedMemorySize, SMEM_BYTES);
        cudaFuncSetAttribute(gemm2_mma, cudaFuncAttributeMaxDynamicSharedMemorySize, SMEM_BYTES);
        attrDone = true;
    }

    convert_split<<<dim3(GD / 32, GN / 32, GB), 256>>>(X);
    gemm1_mma<<<dim3(136, 1, GB), 256, SMEM_BYTES>>>(adj);   // triangular tiles
    softmax_split<<<GB * GN, 256>>>();
    gemm2_mma<<<dim3(GD / 128, GN / 128, GB), 256, SMEM_BYTES>>>(out);
}

// round 7
// speedup vs baseline: 1.4364x; 1.2006x over previous
#include <cuda_runtime.h>
#include <cuda_fp16.h>
#include <cstdint>

#define GN 2048
#define GD 512
#define GB 8
#define NEG_INF_F (-9999999.0f)

// ---------------- device scratch (no allocs allowed) ----------------
__device__ float   g_scratch[(size_t)GB * GN * GN];  // masked scores S (fp32)
__device__ __half  g_pf[(size_t)GB * GN * GN];       // softmax probs (fp16, single)
__device__ __half  g_xh[(size_t)GB * GN * GD];       // X hi   [b,n,d]
__device__ __half  g_xl[(size_t)GB * GN * GD];       // X lo   [b,n,d]
__device__ __half  g_xth[(size_t)GB * GD * GN];      // X^T hi [b,d,n]
__device__ __half  g_xtl[(size_t)GB * GD * GN];      // X^T lo [b,d,n]

// ---------------- helpers ----------------
__device__ __forceinline__ uint32_t smem_u32(const void* p) {
    uint32_t a;
    asm("{ .reg .u64 t; cvta.to.shared.u64 t, %1; cvt.u32.u64 %0, t; }" : "=r"(a) : "l"(p));
    return a;
}

#define CP_ASYNC16(dst, src) \
    asm volatile("cp.async.cg.shared.global [%0], [%1], 16;" :: "r"(dst), "l"(src))
#define CP_COMMIT() asm volatile("cp.async.commit_group;" ::: "memory")
#define CP_WAIT0()  asm volatile("cp.async.wait_group 0;" ::: "memory")

__device__ __forceinline__ void ldsm4(uint32_t* r, uint32_t addr) {
    asm volatile("ldmatrix.sync.aligned.m8n8.x4.shared.b16 {%0,%1,%2,%3}, [%4];"
                 : "=r"(r[0]), "=r"(r[1]), "=r"(r[2]), "=r"(r[3]) : "r"(addr));
}

__device__ __forceinline__ void mma16816(float* c, const uint32_t* a, const uint32_t* b) {
    asm volatile(
        "mma.sync.aligned.m16n8k16.row.col.f32.f16.f16.f32 "
        "{%0,%1,%2,%3}, {%4,%5,%6,%7}, {%8,%9}, {%0,%1,%2,%3};"
        : "+f"(c[0]), "+f"(c[1]), "+f"(c[2]), "+f"(c[3])
        : "r"(a[0]), "r"(a[1]), "r"(a[2]), "r"(a[3]), "r"(b[0]), "r"(b[1]));
}

// ---------------- smem layout ----------------
// Per stream tile: 128 rows x 32 fp16, row stride 40 elems (80B) -> conflict-free ldmatrix.
#define ROW_B    80
#define STREAM_B (128 * ROW_B)              // 10240 B
#define SMEM_G1  (2 * 4 * STREAM_B)         // 81920 B (Ah, Al, Bh, Bl) x 2 stages
#define SMEM_G2  (2 * 3 * STREAM_B)         // 61440 B (A,  Bh, Bl)     x 2 stages

// Load one stage (k-chunk of 32) with cp.async. 256 threads. APL = A planes (1|2).
template <int APL>
__device__ __forceinline__ void load_stage(uint32_t smemStage,
                                           const __half* a_hi, const __half* a_lo,
                                           int ldA,
                                           const __half* b_hi, const __half* b_lo,
                                           int ldB, int k0) {
    const int t = threadIdx.x;
    const __half* srcs[4];
    int lds[4];
    srcs[0] = a_hi; lds[0] = ldA;
    if (APL == 2) { srcs[1] = a_lo; lds[1] = ldA; }
    srcs[APL]     = b_hi; lds[APL]     = ldB;
    srcs[APL + 1] = b_lo; lds[APL + 1] = ldB;
#pragma unroll
    for (int st = 0; st < APL + 2; st++) {
#pragma unroll
        for (int rep = 0; rep < 2; rep++) {
            int c   = t + rep * 256;          // 0..511
            int row = c >> 2;                 // 0..127
            int k8  = c & 3;                  // 16B chunk within 32-elem row
            uint32_t d = smemStage + st * STREAM_B + row * ROW_B + k8 * 16;
            const __half* s = srcs[st] + (size_t)row * lds[st] + k0 + k8 * 8;
            CP_ASYNC16(d, s);
        }
    }
}

// Core: acc[2][8][4] += A(128 x K) * B(128 x K)^T, fp16 split emulation.
// APL=2: 3 MMA terms (ah*bh + ah*bl + al*bh). APL=1: 2 terms (a*bh + a*bl).
// Warp layout 4(m) x 2(n); warp tile 32x64; double-buffered cp.async.
template <int APL>
__device__ __forceinline__ void gemm_core(uint32_t sb,
                                          const __half* a_hi, const __half* a_lo,
                                          int ldA,
                                          const __half* b_hi, const __half* b_lo,
                                          int ldB, int ksteps, float acc[2][8][4]) {
    const int STAGE_B = (APL + 2) * STREAM_B;
    const int l = threadIdx.x & 31;
    const int w = threadIdx.x >> 5;
    const int wm = (w & 3) * 32;
    const int wn = (w >> 2) * 64;

    const int aRow = wm + (l & 15);
    const int aCb  = (l >> 4) * 16;
    const int bRow = wn + (l & 7) + ((l >> 4) & 1) * 8;
    const int bCb  = ((l >> 3) & 1) * 16;

    load_stage<APL>(sb, a_hi, a_lo, ldA, b_hi, b_lo, ldB, 0);
    CP_COMMIT();

#pragma unroll 1
    for (int i = 0; i < ksteps; i++) {
        CP_WAIT0();
        __syncthreads();

        if (i + 1 < ksteps) {
            load_stage<APL>(sb + ((i + 1) & 1) * STAGE_B,
                            a_hi, a_lo, ldA, b_hi, b_lo, ldB, (i + 1) * 32);
            CP_COMMIT();
        }

        const uint32_t stg = sb + (i & 1) * STAGE_B;
#pragma unroll
        for (int s = 0; s < 2; s++) {
            uint32_t ah[2][4], al[2][4];
#pragma unroll
            for (int mf = 0; mf < 2; mf++) {
                uint32_t ad = stg + (aRow + mf * 16) * ROW_B + s * 32 + aCb;
                ldsm4(ah[mf], ad);
                if (APL == 2) ldsm4(al[mf], ad + STREAM_B);
            }
            uint32_t bh[4][4], bl[4][4];
#pragma unroll
            for (int nq = 0; nq < 4; nq++) {
                uint32_t bd = stg + APL * STREAM_B + (bRow + nq * 16) * ROW_B + s * 32 + bCb;
                ldsm4(bh[nq], bd);
                ldsm4(bl[nq], bd + STREAM_B);
            }
#pragma unroll
            for (int mf = 0; mf < 2; mf++)
#pragma unroll
                for (int nq = 0; nq < 4; nq++)
#pragma unroll
                    for (int h = 0; h < 2; h++)
                        mma16816(acc[mf][nq * 2 + h], ah[mf], &bh[nq][h * 2]); // hi*hi
#pragma unroll
            for (int mf = 0; mf < 2; mf++)
#pragma unroll
                for (int nq = 0; nq < 4; nq++)
#pragma unroll
                    for (int h = 0; h < 2; h++)
                        mma16816(acc[mf][nq * 2 + h], ah[mf], &bl[nq][h * 2]); // hi*lo
            if (APL == 2) {
#pragma unroll
                for (int mf = 0; mf < 2; mf++)
#pragma unroll
                    for (int nq = 0; nq < 4; nq++)
#pragma unroll
                        for (int h = 0; h < 2; h++)
                            mma16816(acc[mf][nq * 2 + h], al[mf], &bh[nq][h * 2]); // lo*hi
            }
        }
    }
}

// ---------------------------------------------------------------------------
// Kernel 0: split X into fp16 hi/lo, plus transposed copies.
// ---------------------------------------------------------------------------
__global__ __launch_bounds__(256) void convert_split(const float* __restrict__ X) {
    __shared__ float tile[32][33];
    const int b  = blockIdx.z;
    const int d0 = blockIdx.x * 32;
    const int n0 = blockIdx.y * 32;
    const int tx = threadIdx.x & 31;
    const int ty = threadIdx.x >> 5;
    const float* Xb = X + (size_t)b * GN * GD;

#pragma unroll
    for (int k = 0; k < 4; k++) {
        int n = n0 + ty + k * 8;
        float v = Xb[(size_t)n * GD + d0 + tx];
        tile[ty + k * 8][tx] = v;
        __half h = __float2half(v);
        float lo = v - __half2float(h);
        size_t idx = ((size_t)b * GN + n) * GD + d0 + tx;
        g_xh[idx] = h;
        g_xl[idx] = __float2half(lo);
    }
    __syncthreads();
#pragma unroll
    for (int k = 0; k < 4; k++) {
        int d = d0 + ty + k * 8;
        float v = tile[tx][ty + k * 8];
        __half h = __float2half(v);
        float lo = v - __half2float(h);
        size_t idx = ((size_t)b * GD + d) * GN + n0 + tx;
        g_xth[idx] = h;
        g_xtl[idx] = __float2half(lo);
    }
}

// ---------------------------------------------------------------------------
// Kernel 1: S = X X^T masked by adj (+self) -> g_scratch (fp32).
// SYMMETRIC: compute only upper-triangular tile pairs (R <= C), write both
// (R,C) and its transpose (C,R) with their own adjacency masks.
// ---------------------------------------------------------------------------
__global__ __launch_bounds__(256, 2) void gemm1_mma(const int* __restrict__ adj) {
    extern __shared__ char smem[];
    const uint32_t sb = smem_u32(smem);
    const int b = blockIdx.z;

    int rem = blockIdx.x;
    int R = 0;
    while (rem >= 16 - R) { rem -= 16 - R; R++; }
    const int C = R + rem;
    const int rowBase = R * 128;
    const int colBase = C * 128;

    float acc[2][8][4] = {};
    gemm_core<2>(sb,
                 g_xh + ((size_t)b * GN + rowBase) * GD,
                 g_xl + ((size_t)b * GN + rowBase) * GD, GD,
                 g_xh + ((size_t)b * GN + colBase) * GD,
                 g_xl + ((size_t)b * GN + colBase) * GD, GD,
                 GD / 32, acc);

    const int l = threadIdx.x & 31;
    const int w = threadIdx.x >> 5;
    const int wm = (w & 3) * 32;
    const int wn = (w >> 2) * 64;
    const int* adjb = adj + (size_t)b * GN * GN;
    float* Sb = g_scratch + (size_t)b * GN * GN;

    // ---- write block (R, C): mask adj[n][m] ----
#pragma unroll
    for (int mf = 0; mf < 2; mf++) {
        const int r0 = rowBase + wm + mf * 16 + (l >> 2);
        const int r1 = r0 + 8;
#pragma unroll
        for (int nf = 0; nf < 8; nf++) {
            const int c = colBase + wn + nf * 8 + (l & 3) * 2;
            int2 a0 = *(const int2*)(adjb + (size_t)r0 * GN + c);
            int2 a1 = *(const int2*)(adjb + (size_t)r1 * GN + c);
            float2 o0, o1;
            o0.x = (a0.x != 0 || r0 == c)     ? acc[mf][nf][0] : NEG_INF_F;
            o0.y = (a0.y != 0 || r0 == c + 1) ? acc[mf][nf][1] : NEG_INF_F;
            o1.x = (a1.x != 0 || r1 == c)     ? acc[mf][nf][2] : NEG_INF_F;
            o1.y = (a1.y != 0 || r1 == c + 1) ? acc[mf][nf][3] : NEG_INF_F;
            *(float2*)(Sb + (size_t)r0 * GN + c) = o0;
            *(float2*)(Sb + (size_t)r1 * GN + c) = o1;
        }
    }

    // ---- mirror block (C, R): S[m][n] = acc^T, mask adj[m][n] ----
    if (C != R) {
        __syncthreads();
        float* T = (float*)smem;             // [128][132] fp32 transpose stage
#pragma unroll
        for (int mf = 0; mf < 2; mf++) {
            const int rl0 = wm + mf * 16 + (l >> 2);
            const int rl1 = rl0 + 8;
#pragma unroll
            for (int nf = 0; nf < 8; nf++) {
                const int cl = wn + nf * 8 + (l & 3) * 2;
                T[(cl)     * 132 + rl0] = acc[mf][nf][0];
                T[(cl + 1) * 132 + rl0] = acc[mf][nf][1];
                T[(cl)     * 132 + rl1] = acc[mf][nf][2];
                T[(cl + 1) * 132 + rl1] = acc[mf][nf][3];
            }
        }
        __syncthreads();
#pragma unroll
        for (int mf = 0; mf < 2; mf++) {
            const int ml0 = wm + mf * 16 + (l >> 2);
            const int ml1 = ml0 + 8;
            const int m0 = colBase + ml0;
            const int m1 = colBase + ml1;
#pragma unroll
            for (int nf = 0; nf < 8; nf++) {
                const int nl = wn + nf * 8 + (l & 3) * 2;
                const int nn = rowBase + nl;
                float2 v0 = make_float2(T[ml0 * 132 + nl], T[ml0 * 132 + nl + 1]);
                float2 v1 = make_float2(T[ml1 * 132 + nl], T[ml1 * 132 + nl + 1]);
                int2 a0 = *(const int2*)(adjb + (size_t)m0 * GN + nn);
                int2 a1 = *(const int2*)(adjb + (size_t)m1 * GN + nn);
                float2 o0, o1;
                o0.x = (a0.x != 0) ? v0.x : NEG_INF_F;
                o0.y = (a0.y != 0) ? v0.y : NEG_INF_F;
                o1.x = (a1.x != 0) ? v1.x : NEG_INF_F;
                o1.y = (a1.y != 0) ? v1.y : NEG_INF_F;
                *(float2*)(Sb + (size_t)m0 * GN + nn) = o0;
                *(float2*)(Sb + (size_t)m1 * GN + nn) = o1;
            }
        }
    }
}

// ---------------------------------------------------------------------------
// Kernel 2: row softmax over g_scratch -> fp16 probs (single plane).
// ---------------------------------------------------------------------------
__device__ __forceinline__ float warpMax(float v) {
#pragma unroll
    for (int o = 16; o > 0; o >>= 1) v = fmaxf(v, __shfl_xor_sync(0xffffffffu, v, o));
    return v;
}
__device__ __forceinline__ float warpSum(float v) {
#pragma unroll
    for (int o = 16; o > 0; o >>= 1) v += __shfl_xor_sync(0xffffffffu, v, o);
    return v;
}

__global__ __launch_bounds__(256) void softmax_split() {
    __shared__ float red[8];
    const size_t row = blockIdx.x;
    const float* p = g_scratch + row * GN;
    const int tid = threadIdx.x;

    float4 v0 = ((const float4*)p)[tid];
    float4 v1 = ((const float4*)p)[tid + 256];

    float m = fmaxf(fmaxf(fmaxf(v0.x, v0.y), fmaxf(v0.z, v0.w)),
                    fmaxf(fmaxf(v1.x, v1.y), fmaxf(v1.z, v1.w)));
    m = warpMax(m);
    if ((tid & 31) == 0) red[tid >> 5] = m;
    __syncthreads();
    m = red[0];
#pragma unroll
    for (int i = 1; i < 8; i++) m = fmaxf(m, red[i]);
    __syncthreads();

    v0.x = expf(v0.x - m); v0.y = expf(v0.y - m);
    v0.z = expf(v0.z - m); v0.w = expf(v0.w - m);
    v1.x = expf(v1.x - m); v1.y = expf(v1.y - m);
    v1.z = expf(v1.z - m); v1.w = expf(v1.w - m);

    float s = (v0.x + v0.y + v0.z + v0.w) + (v1.x + v1.y + v1.z + v1.w);
    s = warpSum(s);
    if ((tid & 31) == 0) red[tid >> 5] = s;
    __syncthreads();
    s = red[0] + red[1] + red[2] + red[3] + red[4] + red[5] + red[6] + red[7];

    const float inv = 1.0f / s;
    __half2* ph = (__half2*)(g_pf + row * GN);
    ph[tid * 2]           = __floats2half2_rn(v0.x * inv, v0.y * inv);
    ph[tid * 2 + 1]       = __floats2half2_rn(v0.z * inv, v0.w * inv);
    ph[(tid + 256) * 2]     = __floats2half2_rn(v1.x * inv, v1.y * inv);
    ph[(tid + 256) * 2 + 1] = __floats2half2_rn(v1.z * inv, v1.w * inv);
}

// ---------------------------------------------------------------------------
// Kernel 3: O = P X. A = P fp16 single plane, B = X^T fp16 hi/lo. 2 MMA terms.
// ---------------------------------------------------------------------------
__global__ __launch_bounds__(256, 2) void gemm2_mma(float* __restrict__ out) {
    extern __shared__ char smem[];
    const uint32_t sb = smem_u32(smem);
    const int b = blockIdx.z;
    const int rowBase = blockIdx.y * 128;   // n
    const int colBase = blockIdx.x * 128;   // d

    float acc[2][8][4] = {};
    gemm_core<1>(sb,
                 g_pf  + ((size_t)b * GN + rowBase) * GN, nullptr, GN,
                 g_xth + ((size_t)b * GD + colBase) * GN,
                 g_xtl + ((size_t)b * GD + colBase) * GN, GN,
                 GN / 32, acc);

    const int l = threadIdx.x & 31;
    const int w = threadIdx.x >> 5;
    const int wm = (w & 3) * 32;
    const int wn = (w >> 2) * 64;
    float* Ob = out + (size_t)b * GN * GD;

#pragma unroll
    for (int mf = 0; mf < 2; mf++) {
        const int r0 = rowBase + wm + mf * 16 + (l >> 2);
        const int r1 = r0 + 8;
#pragma unroll
        for (int nf = 0; nf < 8; nf++) {
            const int c = colBase + wn + nf * 8 + (l & 3) * 2;
            *(float2*)(Ob + (size_t)r0 * GD + c) =
                make_float2(acc[mf][nf][0], acc[mf][nf][1]);
            *(float2*)(Ob + (size_t)r1 * GD + c) =
                make_float2(acc[mf][nf][2], acc[mf][nf][3]);
        }
    }
}

// ---------------------------------------------------------------------------
extern "C" void kernel_launch(void* const* d_in, const int* in_sizes, int n_in,
                              void* d_out, int out_size) {
    const float* X   = (const float*)d_in[0];
    const int*   adj = (const int*)d_in[2];
    float*       out = (float*)d_out;

    static bool attrDone = false;
    if (!attrDone) {
        cudaFuncSetAttribute(gemm1_mma, cudaFuncAttributeMaxDynamicSharedMemorySize, SMEM_G1);
        cudaFuncSetAttribute(gemm2_mma, cudaFuncAttributeMaxDynamicSharedMemorySize, SMEM_G2);
        attrDone = true;
    }

    convert_split<<<dim3(GD / 32, GN / 32, GB), 256>>>(X);
    gemm1_mma<<<dim3(136, 1, GB), 256, SMEM_G1>>>(adj);   // triangular tiles
    softmax_split<<<GB * GN, 256>>>();
    gemm2_mma<<<dim3(GD / 128, GN / 128, GB), 256, SMEM_G2>>>(out);
}

// round 8
// speedup vs baseline: 1.8173x; 1.2652x over previous
#include <cuda_runtime.h>
#include <cuda_fp16.h>
#include <cstdint>

#define GN 2048
#define GD 512
#define GB 8
#define NEG_INF_F (-9999999.0f)

// ---------------- device scratch (no allocs allowed) ----------------
__device__ float   g_scratch[(size_t)GB * GN * GN];  // masked scores S (fp32)
__device__ __half  g_pf[(size_t)GB * GN * GN];       // softmax probs (fp16, single)
__device__ __half  g_xh[(size_t)GB * GN * GD];       // X hi   [b,n,d]
__device__ __half  g_xl[(size_t)GB * GN * GD];       // X lo   [b,n,d]
__device__ __half  g_xth[(size_t)GB * GD * GN];      // X^T hi [b,d,n] (single plane)

// ---------------- helpers ----------------
__device__ __forceinline__ uint32_t smem_u32(const void* p) {
    uint32_t a;
    asm("{ .reg .u64 t; cvta.to.shared.u64 t, %1; cvt.u32.u64 %0, t; }" : "=r"(a) : "l"(p));
    return a;
}

#define CP_ASYNC16(dst, src) \
    asm volatile("cp.async.cg.shared.global [%0], [%1], 16;" :: "r"(dst), "l"(src))
#define CP_COMMIT() asm volatile("cp.async.commit_group;" ::: "memory")
#define CP_WAIT0()  asm volatile("cp.async.wait_group 0;" ::: "memory")

__device__ __forceinline__ void ldsm4(uint32_t* r, uint32_t addr) {
    asm volatile("ldmatrix.sync.aligned.m8n8.x4.shared.b16 {%0,%1,%2,%3}, [%4];"
                 : "=r"(r[0]), "=r"(r[1]), "=r"(r[2]), "=r"(r[3]) : "r"(addr));
}

__device__ __forceinline__ void mma16816(float* c, const uint32_t* a, const uint32_t* b) {
    asm volatile(
        "mma.sync.aligned.m16n8k16.row.col.f32.f16.f16.f32 "
        "{%0,%1,%2,%3}, {%4,%5,%6,%7}, {%8,%9}, {%0,%1,%2,%3};"
        : "+f"(c[0]), "+f"(c[1]), "+f"(c[2]), "+f"(c[3])
        : "r"(a[0]), "r"(a[1]), "r"(a[2]), "r"(a[3]), "r"(b[0]), "r"(b[1]));
}

// ---------------- smem layout ----------------
// Per stream tile: 128 rows x 32 fp16, row stride 40 elems (80B) -> conflict-free ldmatrix.
#define ROW_B    80
#define STREAM_B (128 * ROW_B)              // 10240 B
#define SMEM_G1  (2 * 4 * STREAM_B)         // 81920 B (Ah, Al, Bh, Bl) x 2 stages
#define SMEM_G2  (2 * 2 * STREAM_B)         // 40960 B (A, B)           x 2 stages

// Load one stage (k-chunk of 32). APL/BPL = planes per operand (1|2).
template <int APL, int BPL>
__device__ __forceinline__ void load_stage(uint32_t smemStage,
                                           const __half* a_hi, const __half* a_lo,
                                           int ldA,
                                           const __half* b_hi, const __half* b_lo,
                                           int ldB, int k0) {
    const int t = threadIdx.x;
    const __half* srcs[4];
    int lds[4];
    srcs[0] = a_hi; lds[0] = ldA;
    if (APL == 2) { srcs[1] = a_lo; lds[1] = ldA; }
    srcs[APL] = b_hi; lds[APL] = ldB;
    if (BPL == 2) { srcs[APL + 1] = b_lo; lds[APL + 1] = ldB; }
#pragma unroll
    for (int st = 0; st < APL + BPL; st++) {
#pragma unroll
        for (int rep = 0; rep < 2; rep++) {
            int c   = t + rep * 256;          // 0..511
            int row = c >> 2;                 // 0..127
            int k8  = c & 3;                  // 16B chunk within 32-elem row
            uint32_t d = smemStage + st * STREAM_B + row * ROW_B + k8 * 16;
            const __half* s = srcs[st] + (size_t)row * lds[st] + k0 + k8 * 8;
            CP_ASYNC16(d, s);
        }
    }
}

// Core: acc[2][8][4] += A(128 x K) * B(128 x K)^T, fp16 split emulation.
// Terms: ah*bh always; ah*bl if BPL==2; al*bh if APL==2.
// Warp layout 4(m) x 2(n); warp tile 32x64; double-buffered cp.async.
template <int APL, int BPL>
__device__ __forceinline__ void gemm_core(uint32_t sb,
                                          const __half* a_hi, const __half* a_lo,
                                          int ldA,
                                          const __half* b_hi, const __half* b_lo,
                                          int ldB, int ksteps, float acc[2][8][4]) {
    const int STAGE_B = (APL + BPL) * STREAM_B;
    const int l = threadIdx.x & 31;
    const int w = threadIdx.x >> 5;
    const int wm = (w & 3) * 32;
    const int wn = (w >> 2) * 64;

    const int aRow = wm + (l & 15);
    const int aCb  = (l >> 4) * 16;
    const int bRow = wn + (l & 7) + ((l >> 4) & 1) * 8;
    const int bCb  = ((l >> 3) & 1) * 16;

    load_stage<APL, BPL>(sb, a_hi, a_lo, ldA, b_hi, b_lo, ldB, 0);
    CP_COMMIT();

#pragma unroll 1
    for (int i = 0; i < ksteps; i++) {
        CP_WAIT0();
        __syncthreads();

        if (i + 1 < ksteps) {
            load_stage<APL, BPL>(sb + ((i + 1) & 1) * STAGE_B,
                                 a_hi, a_lo, ldA, b_hi, b_lo, ldB, (i + 1) * 32);
            CP_COMMIT();
        }

        const uint32_t stg = sb + (i & 1) * STAGE_B;
#pragma unroll
        for (int s = 0; s < 2; s++) {
            uint32_t ah[2][4], al[2][4];
#pragma unroll
            for (int mf = 0; mf < 2; mf++) {
                uint32_t ad = stg + (aRow + mf * 16) * ROW_B + s * 32 + aCb;
                ldsm4(ah[mf], ad);
                if (APL == 2) ldsm4(al[mf], ad + STREAM_B);
            }
            uint32_t bh[4][4], bl[4][4];
#pragma unroll
            for (int nq = 0; nq < 4; nq++) {
                uint32_t bd = stg + APL * STREAM_B + (bRow + nq * 16) * ROW_B + s * 32 + bCb;
                ldsm4(bh[nq], bd);
                if (BPL == 2) ldsm4(bl[nq], bd + STREAM_B);
            }
#pragma unroll
            for (int mf = 0; mf < 2; mf++)
#pragma unroll
                for (int nq = 0; nq < 4; nq++)
#pragma unroll
                    for (int h = 0; h < 2; h++)
                        mma16816(acc[mf][nq * 2 + h], ah[mf], &bh[nq][h * 2]); // hi*hi
            if (BPL == 2) {
#pragma unroll
                for (int mf = 0; mf < 2; mf++)
#pragma unroll
                    for (int nq = 0; nq < 4; nq++)
#pragma unroll
                        for (int h = 0; h < 2; h++)
                            mma16816(acc[mf][nq * 2 + h], ah[mf], &bl[nq][h * 2]); // hi*lo
            }
            if (APL == 2) {
#pragma unroll
                for (int mf = 0; mf < 2; mf++)
#pragma unroll
                    for (int nq = 0; nq < 4; nq++)
#pragma unroll
                        for (int h = 0; h < 2; h++)
                            mma16816(acc[mf][nq * 2 + h], al[mf], &bh[nq][h * 2]); // lo*hi
            }
        }
    }
}

// ---------------------------------------------------------------------------
// Kernel 0: split X into fp16 hi/lo, plus transposed hi copy.
// ---------------------------------------------------------------------------
__global__ __launch_bounds__(256) void convert_split(const float* __restrict__ X) {
    __shared__ float tile[32][33];
    const int b  = blockIdx.z;
    const int d0 = blockIdx.x * 32;
    const int n0 = blockIdx.y * 32;
    const int tx = threadIdx.x & 31;
    const int ty = threadIdx.x >> 5;
    const float* Xb = X + (size_t)b * GN * GD;

#pragma unroll
    for (int k = 0; k < 4; k++) {
        int n = n0 + ty + k * 8;
        float v = Xb[(size_t)n * GD + d0 + tx];
        tile[ty + k * 8][tx] = v;
        __half h = __float2half(v);
        float lo = v - __half2float(h);
        size_t idx = ((size_t)b * GN + n) * GD + d0 + tx;
        g_xh[idx] = h;
        g_xl[idx] = __float2half(lo);
    }
    __syncthreads();
#pragma unroll
    for (int k = 0; k < 4; k++) {
        int d = d0 + ty + k * 8;
        float v = tile[tx][ty + k * 8];
        size_t idx = ((size_t)b * GD + d) * GN + n0 + tx;
        g_xth[idx] = __float2half(v);
    }
}

// ---------------------------------------------------------------------------
// Kernel 1: S = X X^T masked by adj (+self) -> g_scratch (fp32).
// SYMMETRIC: compute only upper-triangular tile pairs (R <= C), write both
// (R,C) and its transpose (C,R) with their own adjacency masks.
// ---------------------------------------------------------------------------
__global__ __launch_bounds__(256, 2) void gemm1_mma(const int* __restrict__ adj) {
    extern __shared__ char smem[];
    const uint32_t sb = smem_u32(smem);
    const int b = blockIdx.z;

    int rem = blockIdx.x;
    int R = 0;
    while (rem >= 16 - R) { rem -= 16 - R; R++; }
    const int C = R + rem;
    const int rowBase = R * 128;
    const int colBase = C * 128;

    float acc[2][8][4] = {};
    gemm_core<2, 2>(sb,
                    g_xh + ((size_t)b * GN + rowBase) * GD,
                    g_xl + ((size_t)b * GN + rowBase) * GD, GD,
                    g_xh + ((size_t)b * GN + colBase) * GD,
                    g_xl + ((size_t)b * GN + colBase) * GD, GD,
                    GD / 32, acc);

    const int l = threadIdx.x & 31;
    const int w = threadIdx.x >> 5;
    const int wm = (w & 3) * 32;
    const int wn = (w >> 2) * 64;
    const int* adjb = adj + (size_t)b * GN * GN;
    float* Sb = g_scratch + (size_t)b * GN * GN;

    // ---- write block (R, C): mask adj[n][m] ----
#pragma unroll
    for (int mf = 0; mf < 2; mf++) {
        const int r0 = rowBase + wm + mf * 16 + (l >> 2);
        const int r1 = r0 + 8;
#pragma unroll
        for (int nf = 0; nf < 8; nf++) {
            const int c = colBase + wn + nf * 8 + (l & 3) * 2;
            int2 a0 = *(const int2*)(adjb + (size_t)r0 * GN + c);
            int2 a1 = *(const int2*)(adjb + (size_t)r1 * GN + c);
            float2 o0, o1;
            o0.x = (a0.x != 0 || r0 == c)     ? acc[mf][nf][0] : NEG_INF_F;
            o0.y = (a0.y != 0 || r0 == c + 1) ? acc[mf][nf][1] : NEG_INF_F;
            o1.x = (a1.x != 0 || r1 == c)     ? acc[mf][nf][2] : NEG_INF_F;
            o1.y = (a1.y != 0 || r1 == c + 1) ? acc[mf][nf][3] : NEG_INF_F;
            *(float2*)(Sb + (size_t)r0 * GN + c) = o0;
            *(float2*)(Sb + (size_t)r1 * GN + c) = o1;
        }
    }

    // ---- mirror block (C, R): S[m][n] = acc^T, mask adj[m][n] ----
    if (C != R) {
        __syncthreads();
        float* T = (float*)smem;             // [128][132] fp32 transpose stage
#pragma unroll
        for (int mf = 0; mf < 2; mf++) {
            const int rl0 = wm + mf * 16 + (l >> 2);
            const int rl1 = rl0 + 8;
#pragma unroll
            for (int nf = 0; nf < 8; nf++) {
                const int cl = wn + nf * 8 + (l & 3) * 2;
                T[(cl)     * 132 + rl0] = acc[mf][nf][0];
                T[(cl + 1) * 132 + rl0] = acc[mf][nf][1];
                T[(cl)     * 132 + rl1] = acc[mf][nf][2];
                T[(cl + 1) * 132 + rl1] = acc[mf][nf][3];
            }
        }
        __syncthreads();
#pragma unroll
        for (int mf = 0; mf < 2; mf++) {
            const int ml0 = wm + mf * 16 + (l >> 2);
            const int ml1 = ml0 + 8;
            const int m0 = colBase + ml0;
            const int m1 = colBase + ml1;
#pragma unroll
            for (int nf = 0; nf < 8; nf++) {
                const int nl = wn + nf * 8 + (l & 3) * 2;
                const int nn = rowBase + nl;
                float2 v0 = make_float2(T[ml0 * 132 + nl], T[ml0 * 132 + nl + 1]);
                float2 v1 = make_float2(T[ml1 * 132 + nl], T[ml1 * 132 + nl + 1]);
                int2 a0 = *(const int2*)(adjb + (size_t)m0 * GN + nn);
                int2 a1 = *(const int2*)(adjb + (size_t)m1 * GN + nn);
                float2 o0, o1;
                o0.x = (a0.x != 0) ? v0.x : NEG_INF_F;
                o0.y = (a0.y != 0) ? v0.y : NEG_INF_F;
                o1.x = (a1.x != 0) ? v1.x : NEG_INF_F;
                o1.y = (a1.y != 0) ? v1.y : NEG_INF_F;
                *(float2*)(Sb + (size_t)m0 * GN + nn) = o0;
                *(float2*)(Sb + (size_t)m1 * GN + nn) = o1;
            }
        }
    }
}

// ---------------------------------------------------------------------------
// Kernel 2: row softmax over g_scratch -> fp16 probs (single plane).
// ---------------------------------------------------------------------------
__device__ __forceinline__ float warpMax(float v) {
#pragma unroll
    for (int o = 16; o > 0; o >>= 1) v = fmaxf(v, __shfl_xor_sync(0xffffffffu, v, o));
    return v;
}
__device__ __forceinline__ float warpSum(float v) {
#pragma unroll
    for (int o = 16; o > 0; o >>= 1) v += __shfl_xor_sync(0xffffffffu, v, o);
    return v;
}

__global__ __launch_bounds__(256) void softmax_split() {
    __shared__ float red[8];
    const size_t row = blockIdx.x;
    const float* p = g_scratch + row * GN;
    const int tid = threadIdx.x;

    float4 v0 = ((const float4*)p)[tid];
    float4 v1 = ((const float4*)p)[tid + 256];

    float m = fmaxf(fmaxf(fmaxf(v0.x, v0.y), fmaxf(v0.z, v0.w)),
                    fmaxf(fmaxf(v1.x, v1.y), fmaxf(v1.z, v1.w)));
    m = warpMax(m);
    if ((tid & 31) == 0) red[tid >> 5] = m;
    __syncthreads();
    m = red[0];
#pragma unroll
    for (int i = 1; i < 8; i++) m = fmaxf(m, red[i]);
    __syncthreads();

    v0.x = expf(v0.x - m); v0.y = expf(v0.y - m);
    v0.z = expf(v0.z - m); v0.w = expf(v0.w - m);
    v1.x = expf(v1.x - m); v1.y = expf(v1.y - m);
    v1.z = expf(v1.z - m); v1.w = expf(v1.w - m);

    float s = (v0.x + v0.y + v0.z + v0.w) + (v1.x + v1.y + v1.z + v1.w);
    s = warpSum(s);
    if ((tid & 31) == 0) red[tid >> 5] = s;
    __syncthreads();
    s = red[0] + red[1] + red[2] + red[3] + red[4] + red[5] + red[6] + red[7];

    const float inv = 1.0f / s;
    __half2* ph = (__half2*)(g_pf + row * GN);
    ph[tid * 2]             = __floats2half2_rn(v0.x * inv, v0.y * inv);
    ph[tid * 2 + 1]         = __floats2half2_rn(v0.z * inv, v0.w * inv);
    ph[(tid + 256) * 2]     = __floats2half2_rn(v1.x * inv, v1.y * inv);
    ph[(tid + 256) * 2 + 1] = __floats2half2_rn(v1.z * inv, v1.w * inv);
}

// ---------------------------------------------------------------------------
// Kernel 3: O = P X. A = P fp16, B = X^T fp16 (both single plane). 1 MMA term.
// ---------------------------------------------------------------------------
__global__ __launch_bounds__(256, 2) void gemm2_mma(float* __restrict__ out) {
    extern __shared__ char smem[];
    const uint32_t sb = smem_u32(smem);
    const int b = blockIdx.z;
    const int rowBase = blockIdx.y * 128;   // n
    const int colBase = blockIdx.x * 128;   // d

    float acc[2][8][4] = {};
    gemm_core<1, 1>(sb,
                    g_pf  + ((size_t)b * GN + rowBase) * GN, nullptr, GN,
                    g_xth + ((size_t)b * GD + colBase) * GN, nullptr, GN,
                    GN / 32, acc);

    const int l = threadIdx.x & 31;
    const int w = threadIdx.x >> 5;
    const int wm = (w & 3) * 32;
    const int wn = (w >> 2) * 64;
    float* Ob = out + (size_t)b * GN * GD;

#pragma unroll
    for (int mf = 0; mf < 2; mf++) {
        const int r0 = rowBase + wm + mf * 16 + (l >> 2);
        const int r1 = r0 + 8;
#pragma unroll
        for (int nf = 0; nf < 8; nf++) {
            const int c = colBase + wn + nf * 8 + (l & 3) * 2;
            *(float2*)(Ob + (size_t)r0 * GD + c) =
                make_float2(acc[mf][nf][0], acc[mf][nf][1]);
            *(float2*)(Ob + (size_t)r1 * GD + c) =
                make_float2(acc[mf][nf][2], acc[mf][nf][3]);
        }
    }
}

// ---------------------------------------------------------------------------
extern "C" void kernel_launch(void* const* d_in, const int* in_sizes, int n_in,
                              void* d_out, int out_size) {
    const float* X   = (const float*)d_in[0];
    const int*   adj = (const int*)d_in[2];
    float*       out = (float*)d_out;

    static bool attrDone = false;
    if (!attrDone) {
        cudaFuncSetAttribute(gemm1_mma, cudaFuncAttributeMaxDynamicSharedMemorySize, SMEM_G1);
        cudaFuncSetAttribute(gemm2_mma, cudaFuncAttributeMaxDynamicSharedMemorySize, SMEM_G2);
        attrDone = true;
    }

    convert_split<<<dim3(GD / 32, GN / 32, GB), 256>>>(X);
    gemm1_mma<<<dim3(136, 1, GB), 256, SMEM_G1>>>(adj);   // triangular tiles
    softmax_split<<<GB * GN, 256>>>();
    gemm2_mma<<<dim3(GD / 128, GN / 128, GB), 256, SMEM_G2>>>(out);
}

// round 9
// speedup vs baseline: 2.0615x; 1.1344x over previous
#include <cuda_runtime.h>
#include <cuda_fp16.h>
#include <cstdint>

#define GN 2048
#define GD 512
#define GB 8
#define NEG_INF_F (-9999999.0f)

// ---------------- device scratch (no allocs allowed) ----------------
__device__ float   g_scratch[(size_t)GB * GN * GN];  // masked scores S (fp32)
__device__ __half  g_pf[(size_t)GB * GN * GN];       // softmax probs (fp16, single)
__device__ __half  g_xh[(size_t)GB * GN * GD];       // X hi   [b,n,d]
__device__ __half  g_xl[(size_t)GB * GN * GD];       // X lo   [b,n,d]
__device__ __half  g_xth[(size_t)GB * GD * GN];      // X^T hi [b,d,n] (single plane)

// ---------------- helpers ----------------
__device__ __forceinline__ uint32_t smem_u32(const void* p) {
    uint32_t a;
    asm("{ .reg .u64 t; cvta.to.shared.u64 t, %1; cvt.u32.u64 %0, t; }" : "=r"(a) : "l"(p));
    return a;
}

#define CP_ASYNC16(dst, src) \
    asm volatile("cp.async.cg.shared.global [%0], [%1], 16;" :: "r"(dst), "l"(src))
#define CP_COMMIT() asm volatile("cp.async.commit_group;" ::: "memory")
#define CP_WAIT0()  asm volatile("cp.async.wait_group 0;" ::: "memory")

__device__ __forceinline__ void ldsm4(uint32_t* r, uint32_t addr) {
    asm volatile("ldmatrix.sync.aligned.m8n8.x4.shared.b16 {%0,%1,%2,%3}, [%4];"
                 : "=r"(r[0]), "=r"(r[1]), "=r"(r[2]), "=r"(r[3]) : "r"(addr));
}

__device__ __forceinline__ void mma16816(float* c, const uint32_t* a, const uint32_t* b) {
    asm volatile(
        "mma.sync.aligned.m16n8k16.row.col.f32.f16.f16.f32 "
        "{%0,%1,%2,%3}, {%4,%5,%6,%7}, {%8,%9}, {%0,%1,%2,%3};"
        : "+f"(c[0]), "+f"(c[1]), "+f"(c[2]), "+f"(c[3])
        : "r"(a[0]), "r"(a[1]), "r"(a[2]), "r"(a[3]), "r"(b[0]), "r"(b[1]));
}

// ---------------- smem layout ----------------
// Per stream tile: 128 rows x 32 fp16, row stride 40 elems (80B) -> conflict-free ldmatrix.
#define ROW_B    80
#define STREAM_B (128 * ROW_B)              // 10240 B
// gemm1: (Ah, Bh, Bl) x 2 stages = 61440 B; padded to 69632 so the fp32
// 128x132 transpose stage (67584 B) in the mirror epilogue fits.
#define SMEM_G1  69632
#define SMEM_G2  (2 * 2 * STREAM_B)         // 40960 B (A, B) x 2 stages

// Load one stage (k-chunk of 32). APL/BPL = planes per operand (1|2).
template <int APL, int BPL>
__device__ __forceinline__ void load_stage(uint32_t smemStage,
                                           const __half* a_hi, const __half* a_lo,
                                           int ldA,
                                           const __half* b_hi, const __half* b_lo,
                                           int ldB, int k0) {
    const int t = threadIdx.x;
    const __half* srcs[4];
    int lds[4];
    srcs[0] = a_hi; lds[0] = ldA;
    if (APL == 2) { srcs[1] = a_lo; lds[1] = ldA; }
    srcs[APL] = b_hi; lds[APL] = ldB;
    if (BPL == 2) { srcs[APL + 1] = b_lo; lds[APL + 1] = ldB; }
#pragma unroll
    for (int st = 0; st < APL + BPL; st++) {
#pragma unroll
        for (int rep = 0; rep < 2; rep++) {
            int c   = t + rep * 256;          // 0..511
            int row = c >> 2;                 // 0..127
            int k8  = c & 3;                  // 16B chunk within 32-elem row
            uint32_t d = smemStage + st * STREAM_B + row * ROW_B + k8 * 16;
            const __half* s = srcs[st] + (size_t)row * lds[st] + k0 + k8 * 8;
            CP_ASYNC16(d, s);
        }
    }
}

// Core: acc[2][8][4] += A(128 x K) * B(128 x K)^T, fp16 split emulation.
// Terms: ah*bh always; ah*bl if BPL==2; al*bh if APL==2.
// Warp layout 4(m) x 2(n); warp tile 32x64; double-buffered cp.async.
template <int APL, int BPL>
__device__ __forceinline__ void gemm_core(uint32_t sb,
                                          const __half* a_hi, const __half* a_lo,
                                          int ldA,
                                          const __half* b_hi, const __half* b_lo,
                                          int ldB, int ksteps, float acc[2][8][4]) {
    const int STAGE_B = (APL + BPL) * STREAM_B;
    const int l = threadIdx.x & 31;
    const int w = threadIdx.x >> 5;
    const int wm = (w & 3) * 32;
    const int wn = (w >> 2) * 64;

    const int aRow = wm + (l & 15);
    const int aCb  = (l >> 4) * 16;
    const int bRow = wn + (l & 7) + ((l >> 4) & 1) * 8;
    const int bCb  = ((l >> 3) & 1) * 16;

    load_stage<APL, BPL>(sb, a_hi, a_lo, ldA, b_hi, b_lo, ldB, 0);
    CP_COMMIT();

#pragma unroll 1
    for (int i = 0; i < ksteps; i++) {
        CP_WAIT0();
        __syncthreads();

        if (i + 1 < ksteps) {
            load_stage<APL, BPL>(sb + ((i + 1) & 1) * STAGE_B,
                                 a_hi, a_lo, ldA, b_hi, b_lo, ldB, (i + 1) * 32);
            CP_COMMIT();
        }

        const uint32_t stg = sb + (i & 1) * STAGE_B;
#pragma unroll
        for (int s = 0; s < 2; s++) {
            uint32_t ah[2][4], al[2][4];
#pragma unroll
            for (int mf = 0; mf < 2; mf++) {
                uint32_t ad = stg + (aRow + mf * 16) * ROW_B + s * 32 + aCb;
                ldsm4(ah[mf], ad);
                if (APL == 2) ldsm4(al[mf], ad + STREAM_B);
            }
            uint32_t bh[4][4], bl[4][4];
#pragma unroll
            for (int nq = 0; nq < 4; nq++) {
                uint32_t bd = stg + APL * STREAM_B + (bRow + nq * 16) * ROW_B + s * 32 + bCb;
                ldsm4(bh[nq], bd);
                if (BPL == 2) ldsm4(bl[nq], bd + STREAM_B);
            }
#pragma unroll
            for (int mf = 0; mf < 2; mf++)
#pragma unroll
                for (int nq = 0; nq < 4; nq++)
#pragma unroll
                    for (int h = 0; h < 2; h++)
                        mma16816(acc[mf][nq * 2 + h], ah[mf], &bh[nq][h * 2]); // hi*hi
            if (BPL == 2) {
#pragma unroll
                for (int mf = 0; mf < 2; mf++)
#pragma unroll
                    for (int nq = 0; nq < 4; nq++)
#pragma unroll
                        for (int h = 0; h < 2; h++)
                            mma16816(acc[mf][nq * 2 + h], ah[mf], &bl[nq][h * 2]); // hi*lo
            }
            if (APL == 2) {
#pragma unroll
                for (int mf = 0; mf < 2; mf++)
#pragma unroll
                    for (int nq = 0; nq < 4; nq++)
#pragma unroll
                        for (int h = 0; h < 2; h++)
                            mma16816(acc[mf][nq * 2 + h], al[mf], &bh[nq][h * 2]); // lo*hi
            }
        }
    }
}

// ---------------------------------------------------------------------------
// Kernel 0: split X into fp16 hi/lo, plus transposed hi copy.
// ---------------------------------------------------------------------------
__global__ __launch_bounds__(256) void convert_split(const float* __restrict__ X) {
    __shared__ float tile[32][33];
    const int b  = blockIdx.z;
    const int d0 = blockIdx.x * 32;
    const int n0 = blockIdx.y * 32;
    const int tx = threadIdx.x & 31;
    const int ty = threadIdx.x >> 5;
    const float* Xb = X + (size_t)b * GN * GD;

#pragma unroll
    for (int k = 0; k < 4; k++) {
        int n = n0 + ty + k * 8;
        float v = Xb[(size_t)n * GD + d0 + tx];
        tile[ty + k * 8][tx] = v;
        __half h = __float2half(v);
        float lo = v - __half2float(h);
        size_t idx = ((size_t)b * GN + n) * GD + d0 + tx;
        g_xh[idx] = h;
        g_xl[idx] = __float2half(lo);
    }
    __syncthreads();
#pragma unroll
    for (int k = 0; k < 4; k++) {
        int d = d0 + ty + k * 8;
        float v = tile[tx][ty + k * 8];
        size_t idx = ((size_t)b * GD + d) * GN + n0 + tx;
        g_xth[idx] = __float2half(v);
    }
}

// ---------------------------------------------------------------------------
// Kernel 1: S = X X^T masked by adj (+self) -> g_scratch (fp32).
// SYMMETRIC triangular tiles; 2-term fp16 split (A hi, B hi+lo).
// ---------------------------------------------------------------------------
__global__ __launch_bounds__(256, 2) void gemm1_mma(const int* __restrict__ adj) {
    extern __shared__ char smem[];
    const uint32_t sb = smem_u32(smem);
    const int b = blockIdx.z;

    int rem = blockIdx.x;
    int R = 0;
    while (rem >= 16 - R) { rem -= 16 - R; R++; }
    const int C = R + rem;
    const int rowBase = R * 128;
    const int colBase = C * 128;

    float acc[2][8][4] = {};
    gemm_core<1, 2>(sb,
                    g_xh + ((size_t)b * GN + rowBase) * GD, nullptr, GD,
                    g_xh + ((size_t)b * GN + colBase) * GD,
                    g_xl + ((size_t)b * GN + colBase) * GD, GD,
                    GD / 32, acc);

    const int l = threadIdx.x & 31;
    const int w = threadIdx.x >> 5;
    const int wm = (w & 3) * 32;
    const int wn = (w >> 2) * 64;
    const int* adjb = adj + (size_t)b * GN * GN;
    float* Sb = g_scratch + (size_t)b * GN * GN;

    // ---- write block (R, C): mask adj[n][m] ----
#pragma unroll
    for (int mf = 0; mf < 2; mf++) {
        const int r0 = rowBase + wm + mf * 16 + (l >> 2);
        const int r1 = r0 + 8;
#pragma unroll
        for (int nf = 0; nf < 8; nf++) {
            const int c = colBase + wn + nf * 8 + (l & 3) * 2;
            int2 a0 = *(const int2*)(adjb + (size_t)r0 * GN + c);
            int2 a1 = *(const int2*)(adjb + (size_t)r1 * GN + c);
            float2 o0, o1;
            o0.x = (a0.x != 0 || r0 == c)     ? acc[mf][nf][0] : NEG_INF_F;
            o0.y = (a0.y != 0 || r0 == c + 1) ? acc[mf][nf][1] : NEG_INF_F;
            o1.x = (a1.x != 0 || r1 == c)     ? acc[mf][nf][2] : NEG_INF_F;
            o1.y = (a1.y != 0 || r1 == c + 1) ? acc[mf][nf][3] : NEG_INF_F;
            *(float2*)(Sb + (size_t)r0 * GN + c) = o0;
            *(float2*)(Sb + (size_t)r1 * GN + c) = o1;
        }
    }

    // ---- mirror block (C, R): S[m][n] = acc^T, mask adj[m][n] ----
    if (C != R) {
        __syncthreads();
        float* T = (float*)smem;             // [128][132] fp32 transpose stage
#pragma unroll
        for (int mf = 0; mf < 2; mf++) {
            const int rl0 = wm + mf * 16 + (l >> 2);
            const int rl1 = rl0 + 8;
#pragma unroll
            for (int nf = 0; nf < 8; nf++) {
                const int cl = wn + nf * 8 + (l & 3) * 2;
                T[(cl)     * 132 + rl0] = acc[mf][nf][0];
                T[(cl + 1) * 132 + rl0] = acc[mf][nf][1];
                T[(cl)     * 132 + rl1] = acc[mf][nf][2];
                T[(cl + 1) * 132 + rl1] = acc[mf][nf][3];
            }
        }
        __syncthreads();
#pragma unroll
        for (int mf = 0; mf < 2; mf++) {
            const int ml0 = wm + mf * 16 + (l >> 2);
            const int ml1 = ml0 + 8;
            const int m0 = colBase + ml0;
            const int m1 = colBase + ml1;
#pragma unroll
            for (int nf = 0; nf < 8; nf++) {
                const int nl = wn + nf * 8 + (l & 3) * 2;
                const int nn = rowBase + nl;
                float2 v0 = make_float2(T[ml0 * 132 + nl], T[ml0 * 132 + nl + 1]);
                float2 v1 = make_float2(T[ml1 * 132 + nl], T[ml1 * 132 + nl + 1]);
                int2 a0 = *(const int2*)(adjb + (size_t)m0 * GN + nn);
                int2 a1 = *(const int2*)(adjb + (size_t)m1 * GN + nn);
                float2 o0, o1;
                o0.x = (a0.x != 0) ? v0.x : NEG_INF_F;
                o0.y = (a0.y != 0) ? v0.y : NEG_INF_F;
                o1.x = (a1.x != 0) ? v1.x : NEG_INF_F;
                o1.y = (a1.y != 0) ? v1.y : NEG_INF_F;
                *(float2*)(Sb + (size_t)m0 * GN + nn) = o0;
                *(float2*)(Sb + (size_t)m1 * GN + nn) = o1;
            }
        }
    }
}

// ---------------------------------------------------------------------------
// Kernel 2: row softmax over g_scratch -> fp16 probs (single plane).
// ---------------------------------------------------------------------------
__device__ __forceinline__ float warpMax(float v) {
#pragma unroll
    for (int o = 16; o > 0; o >>= 1) v = fmaxf(v, __shfl_xor_sync(0xffffffffu, v, o));
    return v;
}
__device__ __forceinline__ float warpSum(float v) {
#pragma unroll
    for (int o = 16; o > 0; o >>= 1) v += __shfl_xor_sync(0xffffffffu, v, o);
    return v;
}

__global__ __launch_bounds__(256) void softmax_split() {
    __shared__ float red[8];
    const size_t row = blockIdx.x;
    const float* p = g_scratch + row * GN;
    const int tid = threadIdx.x;

    float4 v0 = ((const float4*)p)[tid];
    float4 v1 = ((const float4*)p)[tid + 256];

    float m = fmaxf(fmaxf(fmaxf(v0.x, v0.y), fmaxf(v0.z, v0.w)),
                    fmaxf(fmaxf(v1.x, v1.y), fmaxf(v1.z, v1.w)));
    m = warpMax(m);
    if ((tid & 31) == 0) red[tid >> 5] = m;
    __syncthreads();
    m = red[0];
#pragma unroll
    for (int i = 1; i < 8; i++) m = fmaxf(m, red[i]);
    __syncthreads();

    v0.x = __expf(v0.x - m); v0.y = __expf(v0.y - m);
    v0.z = __expf(v0.z - m); v0.w = __expf(v0.w - m);
    v1.x = __expf(v1.x - m); v1.y = __expf(v1.y - m);
    v1.z = __expf(v1.z - m); v1.w = __expf(v1.w - m);

    float s = (v0.x + v0.y + v0.z + v0.w) + (v1.x + v1.y + v1.z + v1.w);
    s = warpSum(s);
    if ((tid & 31) == 0) red[tid >> 5] = s;
    __syncthreads();
    s = red[0] + red[1] + red[2] + red[3] + red[4] + red[5] + red[6] + red[7];

    const float inv = 1.0f / s;
    __half2* ph = (__half2*)(g_pf + row * GN);
    ph[tid * 2]             = __floats2half2_rn(v0.x * inv, v0.y * inv);
    ph[tid * 2 + 1]         = __floats2half2_rn(v0.z * inv, v0.w * inv);
    ph[(tid + 256) * 2]     = __floats2half2_rn(v1.x * inv, v1.y * inv);
    ph[(tid + 256) * 2 + 1] = __floats2half2_rn(v1.z * inv, v1.w * inv);
}

// ---------------------------------------------------------------------------
// Kernel 3: O = P X. A = P fp16, B = X^T fp16 (both single plane). 1 MMA term.
// ---------------------------------------------------------------------------
__global__ __launch_bounds__(256, 2) void gemm2_mma(float* __restrict__ out) {
    extern __shared__ char smem[];
    const uint32_t sb = smem_u32(smem);
    const int b = blockIdx.z;
    const int rowBase = blockIdx.y * 128;   // n
    const int colBase = blockIdx.x * 128;   // d

    float acc[2][8][4] = {};
    gemm_core<1, 1>(sb,
                    g_pf  + ((size_t)b * GN + rowBase) * GN, nullptr, GN,
                    g_xth + ((size_t)b * GD + colBase) * GN, nullptr, GN,
                    GN / 32, acc);

    const int l = threadIdx.x & 31;
    const int w = threadIdx.x >> 5;
    const int wm = (w & 3) * 32;
    const int wn = (w >> 2) * 64;
    float* Ob = out + (size_t)b * GN * GD;

#pragma unroll
    for (int mf = 0; mf < 2; mf++) {
        const int r0 = rowBase + wm + mf * 16 + (l >> 2);
        const int r1 = r0 + 8;
#pragma unroll
        for (int nf = 0; nf < 8; nf++) {
            const int c = colBase + wn + nf * 8 + (l & 3) * 2;
            *(float2*)(Ob + (size_t)r0 * GD + c) =
                make_float2(acc[mf][nf][0], acc[mf][nf][1]);
            *(float2*)(Ob + (size_t)r1 * GD + c) =
                make_float2(acc[mf][nf][2], acc[mf][nf][3]);
        }
    }
}

// ---------------------------------------------------------------------------
extern "C" void kernel_launch(void* const* d_in, const int* in_sizes, int n_in,
                              void* d_out, int out_size) {
    const float* X   = (const float*)d_in[0];
    const int*   adj = (const int*)d_in[2];
    float*       out = (float*)d_out;

    static bool attrDone = false;
    if (!attrDone) {
        cudaFuncSetAttribute(gemm1_mma, cudaFuncAttributeMaxDynamicSharedMemorySize, SMEM_G1);
        cudaFuncSetAttribute(gemm2_mma, cudaFuncAttributeMaxDynamicSharedMemorySize, SMEM_G2);
        attrDone = true;
    }

    convert_split<<<dim3(GD / 32, GN / 32, GB), 256>>>(X);
    gemm1_mma<<<dim3(136, 1, GB), 256, SMEM_G1>>>(adj);   // triangular tiles
    softmax_split<<<GB * GN, 256>>>();
    gemm2_mma<<<dim3(GD / 128, GN / 128, GB), 256, SMEM_G2>>>(out);
}

// round 10
// speedup vs baseline: 2.1325x; 1.0344x over previous
#include <cuda_runtime.h>
#include <cuda_fp16.h>
#include <cstdint>

#define GN 2048
#define GD 512
#define GB 8
#define NEG_H (-60000.0f)   // fp16-representable mask value; exp() underflows to 0

// ---------------- device scratch (no allocs allowed) ----------------
__device__ __half  g_pf[(size_t)GB * GN * GN];       // scores -> probs (fp16, in-place)
__device__ __half  g_xh[(size_t)GB * GN * GD];       // X hi   [b,n,d]
__device__ __half  g_xl[(size_t)GB * GN * GD];       // X lo   [b,n,d]
__device__ __half  g_xth[(size_t)GB * GD * GN];      // X^T hi [b,d,n] (single plane)

// ---------------- helpers ----------------
__device__ __forceinline__ uint32_t smem_u32(const void* p) {
    uint32_t a;
    asm("{ .reg .u64 t; cvta.to.shared.u64 t, %1; cvt.u32.u64 %0, t; }" : "=r"(a) : "l"(p));
    return a;
}

#define CP_ASYNC16(dst, src) \
    asm volatile("cp.async.cg.shared.global [%0], [%1], 16;" :: "r"(dst), "l"(src))
#define CP_COMMIT() asm volatile("cp.async.commit_group;" ::: "memory")
#define CP_WAIT0()  asm volatile("cp.async.wait_group 0;" ::: "memory")

__device__ __forceinline__ void ldsm4(uint32_t* r, uint32_t addr) {
    asm volatile("ldmatrix.sync.aligned.m8n8.x4.shared.b16 {%0,%1,%2,%3}, [%4];"
                 : "=r"(r[0]), "=r"(r[1]), "=r"(r[2]), "=r"(r[3]) : "r"(addr));
}

__device__ __forceinline__ void mma16816(float* c, const uint32_t* a, const uint32_t* b) {
    asm volatile(
        "mma.sync.aligned.m16n8k16.row.col.f32.f16.f16.f32 "
        "{%0,%1,%2,%3}, {%4,%5,%6,%7}, {%8,%9}, {%0,%1,%2,%3};"
        : "+f"(c[0]), "+f"(c[1]), "+f"(c[2]), "+f"(c[3])
        : "r"(a[0]), "r"(a[1]), "r"(a[2]), "r"(a[3]), "r"(b[0]), "r"(b[1]));
}

// ---------------- smem layout ----------------
// Per stream tile: 128 rows x 32 fp16, row stride 40 elems (80B) -> conflict-free ldmatrix.
#define ROW_B    80
#define STREAM_B (128 * ROW_B)              // 10240 B
#define SMEM_G1  (2 * 3 * STREAM_B)         // 61440 B (Ah, Bh, Bl) x 2; fp16 T fits
#define SMEM_G2  (2 * 2 * STREAM_B)         // 40960 B (A, B) x 2 stages

// Load one stage (k-chunk of 32). APL/BPL = planes per operand (1|2).
template <int APL, int BPL>
__device__ __forceinline__ void load_stage(uint32_t smemStage,
                                           const __half* a_hi, const __half* a_lo,
                                           int ldA,
                                           const __half* b_hi, const __half* b_lo,
                                           int ldB, int k0) {
    const int t = threadIdx.x;
    const __half* srcs[4];
    int lds[4];
    srcs[0] = a_hi; lds[0] = ldA;
    if (APL == 2) { srcs[1] = a_lo; lds[1] = ldA; }
    srcs[APL] = b_hi; lds[APL] = ldB;
    if (BPL == 2) { srcs[APL + 1] = b_lo; lds[APL + 1] = ldB; }
#pragma unroll
    for (int st = 0; st < APL + BPL; st++) {
#pragma unroll
        for (int rep = 0; rep < 2; rep++) {
            int c   = t + rep * 256;          // 0..511
            int row = c >> 2;                 // 0..127
            int k8  = c & 3;                  // 16B chunk within 32-elem row
            uint32_t d = smemStage + st * STREAM_B + row * ROW_B + k8 * 16;
            const __half* s = srcs[st] + (size_t)row * lds[st] + k0 + k8 * 8;
            CP_ASYNC16(d, s);
        }
    }
}

// Core: acc[2][8][4] += A(128 x K) * B(128 x K)^T, fp16 split emulation.
// Terms: ah*bh always; ah*bl if BPL==2; al*bh if APL==2.
// Warp layout 4(m) x 2(n); warp tile 32x64; double-buffered cp.async.
template <int APL, int BPL>
__device__ __forceinline__ void gemm_core(uint32_t sb,
                                          const __half* a_hi, const __half* a_lo,
                                          int ldA,
                                          const __half* b_hi, const __half* b_lo,
                                          int ldB, int ksteps, float acc[2][8][4]) {
    const int STAGE_B = (APL + BPL) * STREAM_B;
    const int l = threadIdx.x & 31;
    const int w = threadIdx.x >> 5;
    const int wm = (w & 3) * 32;
    const int wn = (w >> 2) * 64;

    const int aRow = wm + (l & 15);
    const int aCb  = (l >> 4) * 16;
    const int bRow = wn + (l & 7) + ((l >> 4) & 1) * 8;
    const int bCb  = ((l >> 3) & 1) * 16;

    load_stage<APL, BPL>(sb, a_hi, a_lo, ldA, b_hi, b_lo, ldB, 0);
    CP_COMMIT();

#pragma unroll 1
    for (int i = 0; i < ksteps; i++) {
        CP_WAIT0();
        __syncthreads();

        if (i + 1 < ksteps) {
            load_stage<APL, BPL>(sb + ((i + 1) & 1) * STAGE_B,
                                 a_hi, a_lo, ldA, b_hi, b_lo, ldB, (i + 1) * 32);
            CP_COMMIT();
        }

        const uint32_t stg = sb + (i & 1) * STAGE_B;
#pragma unroll
        for (int s = 0; s < 2; s++) {
            uint32_t ah[2][4], al[2][4];
#pragma unroll
            for (int mf = 0; mf < 2; mf++) {
                uint32_t ad = stg + (aRow + mf * 16) * ROW_B + s * 32 + aCb;
                ldsm4(ah[mf], ad);
                if (APL == 2) ldsm4(al[mf], ad + STREAM_B);
            }
            uint32_t bh[4][4], bl[4][4];
#pragma unroll
            for (int nq = 0; nq < 4; nq++) {
                uint32_t bd = stg + APL * STREAM_B + (bRow + nq * 16) * ROW_B + s * 32 + bCb;
                ldsm4(bh[nq], bd);
                if (BPL == 2) ldsm4(bl[nq], bd + STREAM_B);
            }
#pragma unroll
            for (int mf = 0; mf < 2; mf++)
#pragma unroll
                for (int nq = 0; nq < 4; nq++)
#pragma unroll
                    for (int h = 0; h < 2; h++)
                        mma16816(acc[mf][nq * 2 + h], ah[mf], &bh[nq][h * 2]); // hi*hi
            if (BPL == 2) {
#pragma unroll
                for (int mf = 0; mf < 2; mf++)
#pragma unroll
                    for (int nq = 0; nq < 4; nq++)
#pragma unroll
                        for (int h = 0; h < 2; h++)
                            mma16816(acc[mf][nq * 2 + h], ah[mf], &bl[nq][h * 2]); // hi*lo
            }
            if (APL == 2) {
#pragma unroll
                for (int mf = 0; mf < 2; mf++)
#pragma unroll
                    for (int nq = 0; nq < 4; nq++)
#pragma unroll
                        for (int h = 0; h < 2; h++)
                            mma16816(acc[mf][nq * 2 + h], al[mf], &bh[nq][h * 2]); // lo*hi
            }
        }
    }
}

// ---------------------------------------------------------------------------
// Kernel 0: split X into fp16 hi/lo, plus transposed hi copy.
// ---------------------------------------------------------------------------
__global__ __launch_bounds__(256) void convert_split(const float* __restrict__ X) {
    __shared__ float tile[32][33];
    const int b  = blockIdx.z;
    const int d0 = blockIdx.x * 32;
    const int n0 = blockIdx.y * 32;
    const int tx = threadIdx.x & 31;
    const int ty = threadIdx.x >> 5;
    const float* Xb = X + (size_t)b * GN * GD;

#pragma unroll
    for (int k = 0; k < 4; k++) {
        int n = n0 + ty + k * 8;
        float v = Xb[(size_t)n * GD + d0 + tx];
        tile[ty + k * 8][tx] = v;
        __half h = __float2half(v);
        float lo = v - __half2float(h);
        size_t idx = ((size_t)b * GN + n) * GD + d0 + tx;
        g_xh[idx] = h;
        g_xl[idx] = __float2half(lo);
    }
    __syncthreads();
#pragma unroll
    for (int k = 0; k < 4; k++) {
        int d = d0 + ty + k * 8;
        float v = tile[tx][ty + k * 8];
        size_t idx = ((size_t)b * GD + d) * GN + n0 + tx;
        g_xth[idx] = __float2half(v);
    }
}

// ---------------------------------------------------------------------------
// Kernel 1: S = X X^T masked by adj (+self) -> g_pf (fp16).
// SYMMETRIC triangular tiles; 2-term fp16 split (A hi, B hi+lo).
// ---------------------------------------------------------------------------
__global__ __launch_bounds__(256, 2) void gemm1_mma(const int* __restrict__ adj) {
    extern __shared__ char smem[];
    const uint32_t sb = smem_u32(smem);
    const int b = blockIdx.z;

    int rem = blockIdx.x;
    int R = 0;
    while (rem >= 16 - R) { rem -= 16 - R; R++; }
    const int C = R + rem;
    const int rowBase = R * 128;
    const int colBase = C * 128;

    float acc[2][8][4] = {};
    gemm_core<1, 2>(sb,
                    g_xh + ((size_t)b * GN + rowBase) * GD, nullptr, GD,
                    g_xh + ((size_t)b * GN + colBase) * GD,
                    g_xl + ((size_t)b * GN + colBase) * GD, GD,
                    GD / 32, acc);

    const int l = threadIdx.x & 31;
    const int w = threadIdx.x >> 5;
    const int wm = (w & 3) * 32;
    const int wn = (w >> 2) * 64;
    const int* adjb = adj + (size_t)b * GN * GN;
    __half* Sb = g_pf + (size_t)b * GN * GN;

    // ---- write block (R, C) as fp16: mask adj[n][m] ----
#pragma unroll
    for (int mf = 0; mf < 2; mf++) {
        const int r0 = rowBase + wm + mf * 16 + (l >> 2);
        const int r1 = r0 + 8;
#pragma unroll
        for (int nf = 0; nf < 8; nf++) {
            const int c = colBase + wn + nf * 8 + (l & 3) * 2;
            int2 a0 = *(const int2*)(adjb + (size_t)r0 * GN + c);
            int2 a1 = *(const int2*)(adjb + (size_t)r1 * GN + c);
            float v00 = (a0.x != 0 || r0 == c)     ? acc[mf][nf][0] : NEG_H;
            float v01 = (a0.y != 0 || r0 == c + 1) ? acc[mf][nf][1] : NEG_H;
            float v10 = (a1.x != 0 || r1 == c)     ? acc[mf][nf][2] : NEG_H;
            float v11 = (a1.y != 0 || r1 == c + 1) ? acc[mf][nf][3] : NEG_H;
            *(__half2*)(Sb + (size_t)r0 * GN + c) = __floats2half2_rn(v00, v01);
            *(__half2*)(Sb + (size_t)r1 * GN + c) = __floats2half2_rn(v10, v11);
        }
    }

    // ---- mirror block (C, R): S[m][n] = acc^T (fp16), mask adj[m][n] ----
    if (C != R) {
        __syncthreads();
        __half* T = (__half*)smem;           // [128][132] fp16 transpose stage
#pragma unroll
        for (int mf = 0; mf < 2; mf++) {
            const int rl0 = wm + mf * 16 + (l >> 2);
            const int rl1 = rl0 + 8;
#pragma unroll
            for (int nf = 0; nf < 8; nf++) {
                const int cl = wn + nf * 8 + (l & 3) * 2;
                T[(cl)     * 132 + rl0] = __float2half(acc[mf][nf][0]);
                T[(cl + 1) * 132 + rl0] = __float2half(acc[mf][nf][1]);
                T[(cl)     * 132 + rl1] = __float2half(acc[mf][nf][2]);
                T[(cl + 1) * 132 + rl1] = __float2half(acc[mf][nf][3]);
            }
        }
        __syncthreads();
#pragma unroll
        for (int mf = 0; mf < 2; mf++) {
            const int ml0 = wm + mf * 16 + (l >> 2);
            const int ml1 = ml0 + 8;
            const int m0 = colBase + ml0;
            const int m1 = colBase + ml1;
#pragma unroll
            for (int nf = 0; nf < 8; nf++) {
                const int nl = wn + nf * 8 + (l & 3) * 2;
                const int nn = rowBase + nl;
                int2 a0 = *(const int2*)(adjb + (size_t)m0 * GN + nn);
                int2 a1 = *(const int2*)(adjb + (size_t)m1 * GN + nn);
                __half2 o0, o1;
                __half negh = __float2half(NEG_H);
                o0.x = (a0.x != 0) ? T[ml0 * 132 + nl]     : negh;
                o0.y = (a0.y != 0) ? T[ml0 * 132 + nl + 1] : negh;
                o1.x = (a1.x != 0) ? T[ml1 * 132 + nl]     : negh;
                o1.y = (a1.y != 0) ? T[ml1 * 132 + nl + 1] : negh;
                *(__half2*)(Sb + (size_t)m0 * GN + nn) = o0;
                *(__half2*)(Sb + (size_t)m1 * GN + nn) = o1;
            }
        }
    }
}

// ---------------------------------------------------------------------------
// Kernel 2: in-place row softmax over fp16 buffer g_pf.
// ---------------------------------------------------------------------------
__device__ __forceinline__ float warpMax(float v) {
#pragma unroll
    for (int o = 16; o > 0; o >>= 1) v = fmaxf(v, __shfl_xor_sync(0xffffffffu, v, o));
    return v;
}
__device__ __forceinline__ float warpSum(float v) {
#pragma unroll
    for (int o = 16; o > 0; o >>= 1) v += __shfl_xor_sync(0xffffffffu, v, o);
    return v;
}

__global__ __launch_bounds__(256) void softmax_inplace() {
    __shared__ float red[8];
    const size_t row = blockIdx.x;
    __half* p = g_pf + row * GN;
    const int tid = threadIdx.x;

    // 8 halfs per thread (one 16B load)
    float4 raw = ((const float4*)p)[tid];
    __half2 h[4];
    h[0] = *(__half2*)&raw.x; h[1] = *(__half2*)&raw.y;
    h[2] = *(__half2*)&raw.z; h[3] = *(__half2*)&raw.w;
    float f[8];
#pragma unroll
    for (int i = 0; i < 4; i++) {
        float2 t = __half22float2(h[i]);
        f[i * 2] = t.x; f[i * 2 + 1] = t.y;
    }

    float m = f[0];
#pragma unroll
    for (int i = 1; i < 8; i++) m = fmaxf(m, f[i]);
    m = warpMax(m);
    if ((tid & 31) == 0) red[tid >> 5] = m;
    __syncthreads();
    m = red[0];
#pragma unroll
    for (int i = 1; i < 8; i++) m = fmaxf(m, red[i]);
    __syncthreads();

    float s = 0.f;
#pragma unroll
    for (int i = 0; i < 8; i++) { f[i] = __expf(f[i] - m); s += f[i]; }
    s = warpSum(s);
    if ((tid & 31) == 0) red[tid >> 5] = s;
    __syncthreads();
    s = red[0] + red[1] + red[2] + red[3] + red[4] + red[5] + red[6] + red[7];

    const float inv = 1.0f / s;
#pragma unroll
    for (int i = 0; i < 4; i++)
        h[i] = __floats2half2_rn(f[i * 2] * inv, f[i * 2 + 1] * inv);
    float4 outv;
    outv.x = *(float*)&h[0]; outv.y = *(float*)&h[1];
    outv.z = *(float*)&h[2]; outv.w = *(float*)&h[3];
    ((float4*)p)[tid] = outv;
}

// ---------------------------------------------------------------------------
// Kernel 3: O = P X. A = P fp16, B = X^T fp16 (both single plane). 1 MMA term.
// ---------------------------------------------------------------------------
__global__ __launch_bounds__(256, 2) void gemm2_mma(float* __restrict__ out) {
    extern __shared__ char smem[];
    const uint32_t sb = smem_u32(smem);
    const int b = blockIdx.z;
    const int rowBase = blockIdx.y * 128;   // n
    const int colBase = blockIdx.x * 128;   // d

    float acc[2][8][4] = {};
    gemm_core<1, 1>(sb,
                    g_pf  + ((size_t)b * GN + rowBase) * GN, nullptr, GN,
                    g_xth + ((size_t)b * GD + colBase) * GN, nullptr, GN,
                    GN / 32, acc);

    const int l = threadIdx.x & 31;
    const int w = threadIdx.x >> 5;
    const int wm = (w & 3) * 32;
    const int wn = (w >> 2) * 64;
    float* Ob = out + (size_t)b * GN * GD;

#pragma unroll
    for (int mf = 0; mf < 2; mf++) {
        const int r0 = rowBase + wm + mf * 16 + (l >> 2);
        const int r1 = r0 + 8;
#pragma unroll
        for (int nf = 0; nf < 8; nf++) {
            const int c = colBase + wn + nf * 8 + (l & 3) * 2;
            *(float2*)(Ob + (size_t)r0 * GD + c) =
                make_float2(acc[mf][nf][0], acc[mf][nf][1]);
            *(float2*)(Ob + (size_t)r1 * GD + c) =
                make_float2(acc[mf][nf][2], acc[mf][nf][3]);
        }
    }
}

// ---------------------------------------------------------------------------
extern "C" void kernel_launch(void* const* d_in, const int* in_sizes, int n_in,
                              void* d_out, int out_size) {
    const float* X   = (const float*)d_in[0];
    const int*   adj = (const int*)d_in[2];
    float*       out = (float*)d_out;

    static bool attrDone = false;
    if (!attrDone) {
        cudaFuncSetAttribute(gemm1_mma, cudaFuncAttributeMaxDynamicSharedMemorySize, SMEM_G1);
        cudaFuncSetAttribute(gemm2_mma, cudaFuncAttributeMaxDynamicSharedMemorySize, SMEM_G2);
        attrDone = true;
    }

    convert_split<<<dim3(GD / 32, GN / 32, GB), 256>>>(X);
    gemm1_mma<<<dim3(136, 1, GB), 256, SMEM_G1>>>(adj);   // triangular tiles
    softmax_inplace<<<GB * GN, 256>>>();
    gemm2_mma<<<dim3(GD / 128, GN / 128, GB), 256, SMEM_G2>>>(out);
}

// round 11
// speedup vs baseline: 2.5000x; 1.1723x over previous
#include <cuda_runtime.h>
#include <cuda_fp16.h>
#include <cstdint>

#define GN 2048
#define GD 512
#define GB 8
#define NEG_H (-60000.0f)   // fp16-representable mask value; exp() underflows to 0

// ---------------- device scratch (no allocs allowed) ----------------
__device__ __half  g_pf[(size_t)GB * GN * GN];       // scores -> probs (fp16, in-place)
__device__ __half  g_xh[(size_t)GB * GN * GD];       // X fp16 [b,n,d]
__device__ __half  g_xth[(size_t)GB * GD * GN];      // X^T fp16 [b,d,n]

// ---------------- helpers ----------------
__device__ __forceinline__ uint32_t smem_u32(const void* p) {
    uint32_t a;
    asm("{ .reg .u64 t; cvta.to.shared.u64 t, %1; cvt.u32.u64 %0, t; }" : "=r"(a) : "l"(p));
    return a;
}

#define CP_ASYNC16(dst, src) \
    asm volatile("cp.async.cg.shared.global [%0], [%1], 16;" :: "r"(dst), "l"(src))
#define CP_COMMIT() asm volatile("cp.async.commit_group;" ::: "memory")
#define CP_WAIT0()  asm volatile("cp.async.wait_group 0;" ::: "memory")

__device__ __forceinline__ void ldsm4(uint32_t* r, uint32_t addr) {
    asm volatile("ldmatrix.sync.aligned.m8n8.x4.shared.b16 {%0,%1,%2,%3}, [%4];"
                 : "=r"(r[0]), "=r"(r[1]), "=r"(r[2]), "=r"(r[3]) : "r"(addr));
}

__device__ __forceinline__ void mma16816(float* c, const uint32_t* a, const uint32_t* b) {
    asm volatile(
        "mma.sync.aligned.m16n8k16.row.col.f32.f16.f16.f32 "
        "{%0,%1,%2,%3}, {%4,%5,%6,%7}, {%8,%9}, {%0,%1,%2,%3};"
        : "+f"(c[0]), "+f"(c[1]), "+f"(c[2]), "+f"(c[3])
        : "r"(a[0]), "r"(a[1]), "r"(a[2]), "r"(a[3]), "r"(b[0]), "r"(b[1]));
}

// ---------------- smem layout ----------------
// Per stream tile: 128 rows x 32 fp16, row stride 40 elems (80B) -> conflict-free ldmatrix.
#define ROW_B    80
#define STREAM_B (128 * ROW_B)        // 10240 B
#define NSTAGE   3
#define STAGE_B  (2 * STREAM_B)       // A, B
#define SMEM_GEMM (NSTAGE * STAGE_B)  // 61440 B -> 2 CTAs/SM; fp16 T (33792 B) fits

// Load one stage (k-chunk of 32): two streams A and B. 256 threads.
__device__ __forceinline__ void load_stage2(uint32_t smemStage,
                                            const __half* a, int ldA,
                                            const __half* b, int ldB, int k0) {
    const int t = threadIdx.x;
    const __half* srcs[2] = {a, b};
    const int lds[2] = {ldA, ldB};
#pragma unroll
    for (int st = 0; st < 2; st++) {
#pragma unroll
        for (int rep = 0; rep < 2; rep++) {
            int c   = t + rep * 256;          // 0..511
            int row = c >> 2;                 // 0..127
            int k8  = c & 3;                  // 16B chunk within 32-elem row
            uint32_t d = smemStage + st * STREAM_B + row * ROW_B + k8 * 16;
            const __half* s = srcs[st] + (size_t)row * lds[st] + k0 + k8 * 8;
            CP_ASYNC16(d, s);
        }
    }
}

// Core: acc[2][8][4] += A(128 x K) * B(128 x K)^T, single fp16 term.
// Warp layout 4(m) x 2(n); warp tile 32x64; 3-stage cp.async pipeline.
__device__ __forceinline__ void gemm_core(uint32_t sb,
                                          const __half* a, int ldA,
                                          const __half* b, int ldB,
                                          int ksteps, float acc[2][8][4]) {
    const int l = threadIdx.x & 31;
    const int w = threadIdx.x >> 5;
    const int wm = (w & 3) * 32;
    const int wn = (w >> 2) * 64;

    const int aRow = wm + (l & 15);
    const int aCb  = (l >> 4) * 16;
    const int bRow = wn + (l & 7) + ((l >> 4) & 1) * 8;
    const int bCb  = ((l >> 3) & 1) * 16;

    // prologue: stages 0 .. NSTAGE-2
#pragma unroll
    for (int s = 0; s < NSTAGE - 1; s++) {
        load_stage2(sb + s * STAGE_B, a, ldA, b, ldB, s * 32);
        CP_COMMIT();
    }

#pragma unroll 1
    for (int i = 0; i < ksteps; i++) {
        if (i + NSTAGE - 1 < ksteps) {
            // NSTAGE-1 groups in flight; leave NSTAGE-2 -> stage i complete
            asm volatile("cp.async.wait_group %0;" :: "n"(NSTAGE - 2) : "memory");
            __syncthreads();   // publish stage i; prove reuse target drained
            load_stage2(sb + ((i + NSTAGE - 1) % NSTAGE) * STAGE_B,
                        a, ldA, b, ldB, (i + NSTAGE - 1) * 32);
            CP_COMMIT();
        } else {
            CP_WAIT0();        // tail: drain everything
            __syncthreads();
        }

        const uint32_t stg = sb + (i % NSTAGE) * STAGE_B;
#pragma unroll
        for (int s = 0; s < 2; s++) {
            uint32_t ah[2][4];
#pragma unroll
            for (int mf = 0; mf < 2; mf++)
                ldsm4(ah[mf], stg + (aRow + mf * 16) * ROW_B + s * 32 + aCb);
            uint32_t bh[4][4];
#pragma unroll
            for (int nq = 0; nq < 4; nq++)
                ldsm4(bh[nq], stg + STREAM_B + (bRow + nq * 16) * ROW_B + s * 32 + bCb);
#pragma unroll
            for (int mf = 0; mf < 2; mf++)
#pragma unroll
                for (int nq = 0; nq < 4; nq++)
#pragma unroll
                    for (int h = 0; h < 2; h++)
                        mma16816(acc[mf][nq * 2 + h], ah[mf], &bh[nq][h * 2]);
        }
    }
}

// ---------------------------------------------------------------------------
// Kernel 0: convert X to fp16, plus transposed copy.
// ---------------------------------------------------------------------------
__global__ __launch_bounds__(256) void convert_split(const float* __restrict__ X) {
    __shared__ float tile[32][33];
    const int b  = blockIdx.z;
    const int d0 = blockIdx.x * 32;
    const int n0 = blockIdx.y * 32;
    const int tx = threadIdx.x & 31;
    const int ty = threadIdx.x >> 5;
    const float* Xb = X + (size_t)b * GN * GD;

#pragma unroll
    for (int k = 0; k < 4; k++) {
        int n = n0 + ty + k * 8;
        float v = Xb[(size_t)n * GD + d0 + tx];
        tile[ty + k * 8][tx] = v;
        g_xh[((size_t)b * GN + n) * GD + d0 + tx] = __float2half(v);
    }
    __syncthreads();
#pragma unroll
    for (int k = 0; k < 4; k++) {
        int d = d0 + ty + k * 8;
        float v = tile[tx][ty + k * 8];
        g_xth[((size_t)b * GD + d) * GN + n0 + tx] = __float2half(v);
    }
}

// ---------------------------------------------------------------------------
// Kernel 1: S = X X^T masked by adj (+self) -> g_pf (fp16).
// SYMMETRIC triangular tiles; single fp16 term.
// ---------------------------------------------------------------------------
__global__ __launch_bounds__(256, 2) void gemm1_mma(const int* __restrict__ adj) {
    extern __shared__ char smem[];
    const uint32_t sb = smem_u32(smem);
    const int b = blockIdx.z;

    int rem = blockIdx.x;
    int R = 0;
    while (rem >= 16 - R) { rem -= 16 - R; R++; }
    const int C = R + rem;
    const int rowBase = R * 128;
    const int colBase = C * 128;

    float acc[2][8][4] = {};
    gemm_core(sb,
              g_xh + ((size_t)b * GN + rowBase) * GD, GD,
              g_xh + ((size_t)b * GN + colBase) * GD, GD,
              GD / 32, acc);

    const int l = threadIdx.x & 31;
    const int w = threadIdx.x >> 5;
    const int wm = (w & 3) * 32;
    const int wn = (w >> 2) * 64;
    const int* adjb = adj + (size_t)b * GN * GN;
    __half* Sb = g_pf + (size_t)b * GN * GN;

    // ---- write block (R, C) as fp16: mask adj[n][m] ----
#pragma unroll
    for (int mf = 0; mf < 2; mf++) {
        const int r0 = rowBase + wm + mf * 16 + (l >> 2);
        const int r1 = r0 + 8;
#pragma unroll
        for (int nf = 0; nf < 8; nf++) {
            const int c = colBase + wn + nf * 8 + (l & 3) * 2;
            int2 a0 = *(const int2*)(adjb + (size_t)r0 * GN + c);
            int2 a1 = *(const int2*)(adjb + (size_t)r1 * GN + c);
            float v00 = (a0.x != 0 || r0 == c)     ? acc[mf][nf][0] : NEG_H;
            float v01 = (a0.y != 0 || r0 == c + 1) ? acc[mf][nf][1] : NEG_H;
            float v10 = (a1.x != 0 || r1 == c)     ? acc[mf][nf][2] : NEG_H;
            float v11 = (a1.y != 0 || r1 == c + 1) ? acc[mf][nf][3] : NEG_H;
            *(__half2*)(Sb + (size_t)r0 * GN + c) = __floats2half2_rn(v00, v01);
            *(__half2*)(Sb + (size_t)r1 * GN + c) = __floats2half2_rn(v10, v11);
        }
    }

    // ---- mirror block (C, R): S[m][n] = acc^T (fp16), mask adj[m][n] ----
    if (C != R) {
        __syncthreads();
        __half* T = (__half*)smem;           // [128][132] fp16 transpose stage
#pragma unroll
        for (int mf = 0; mf < 2; mf++) {
            const int rl0 = wm + mf * 16 + (l >> 2);
            const int rl1 = rl0 + 8;
#pragma unroll
            for (int nf = 0; nf < 8; nf++) {
                const int cl = wn + nf * 8 + (l & 3) * 2;
                T[(cl)     * 132 + rl0] = __float2half(acc[mf][nf][0]);
                T[(cl + 1) * 132 + rl0] = __float2half(acc[mf][nf][1]);
                T[(cl)     * 132 + rl1] = __float2half(acc[mf][nf][2]);
                T[(cl + 1) * 132 + rl1] = __float2half(acc[mf][nf][3]);
            }
        }
        __syncthreads();
#pragma unroll
        for (int mf = 0; mf < 2; mf++) {
            const int ml0 = wm + mf * 16 + (l >> 2);
            const int ml1 = ml0 + 8;
            const int m0 = colBase + ml0;
            const int m1 = colBase + ml1;
#pragma unroll
            for (int nf = 0; nf < 8; nf++) {
                const int nl = wn + nf * 8 + (l & 3) * 2;
                const int nn = rowBase + nl;
                int2 a0 = *(const int2*)(adjb + (size_t)m0 * GN + nn);
                int2 a1 = *(const int2*)(adjb + (size_t)m1 * GN + nn);
                __half2 o0, o1;
                __half negh = __float2half(NEG_H);
                o0.x = (a0.x != 0) ? T[ml0 * 132 + nl]     : negh;
                o0.y = (a0.y != 0) ? T[ml0 * 132 + nl + 1] : negh;
                o1.x = (a1.x != 0) ? T[ml1 * 132 + nl]     : negh;
                o1.y = (a1.y != 0) ? T[ml1 * 132 + nl + 1] : negh;
                *(__half2*)(Sb + (size_t)m0 * GN + nn) = o0;
                *(__half2*)(Sb + (size_t)m1 * GN + nn) = o1;
            }
        }
    }
}

// ---------------------------------------------------------------------------
// Kernel 2: in-place row softmax over fp16 buffer g_pf.
// ---------------------------------------------------------------------------
__device__ __forceinline__ float warpMax(float v) {
#pragma unroll
    for (int o = 16; o > 0; o >>= 1) v = fmaxf(v, __shfl_xor_sync(0xffffffffu, v, o));
    return v;
}
__device__ __forceinline__ float warpSum(float v) {
#pragma unroll
    for (int o = 16; o > 0; o >>= 1) v += __shfl_xor_sync(0xffffffffu, v, o);
    return v;
}

__global__ __launch_bounds__(256) void softmax_inplace() {
    __shared__ float red[8];
    const size_t row = blockIdx.x;
    __half* p = g_pf + row * GN;
    const int tid = threadIdx.x;

    float4 raw = ((const float4*)p)[tid];
    __half2 h[4];
    h[0] = *(__half2*)&raw.x; h[1] = *(__half2*)&raw.y;
    h[2] = *(__half2*)&raw.z; h[3] = *(__half2*)&raw.w;
    float f[8];
#pragma unroll
    for (int i = 0; i < 4; i++) {
        float2 t = __half22float2(h[i]);
        f[i * 2] = t.x; f[i * 2 + 1] = t.y;
    }

    float m = f[0];
#pragma unroll
    for (int i = 1; i < 8; i++) m = fmaxf(m, f[i]);
    m = warpMax(m);
    if ((tid & 31) == 0) red[tid >> 5] = m;
    __syncthreads();
    m = red[0];
#pragma unroll
    for (int i = 1; i < 8; i++) m = fmaxf(m, red[i]);
    __syncthreads();

    float s = 0.f;
#pragma unroll
    for (int i = 0; i < 8; i++) { f[i] = __expf(f[i] - m); s += f[i]; }
    s = warpSum(s);
    if ((tid & 31) == 0) red[tid >> 5] = s;
    __syncthreads();
    s = red[0] + red[1] + red[2] + red[3] + red[4] + red[5] + red[6] + red[7];

    const float inv = 1.0f / s;
#pragma unroll
    for (int i = 0; i < 4; i++)
        h[i] = __floats2half2_rn(f[i * 2] * inv, f[i * 2 + 1] * inv);
    float4 outv;
    outv.x = *(float*)&h[0]; outv.y = *(float*)&h[1];
    outv.z = *(float*)&h[2]; outv.w = *(float*)&h[3];
    ((float4*)p)[tid] = outv;
}

// ---------------------------------------------------------------------------
// Kernel 3: O = P X. A = P fp16, B = X^T fp16. Single MMA term.
// ---------------------------------------------------------------------------
__global__ __launch_bounds__(256, 2) void gemm2_mma(float* __restrict__ out) {
    extern __shared__ char smem[];
    const uint32_t sb = smem_u32(smem);
    const int b = blockIdx.z;
    const int rowBase = blockIdx.y * 128;   // n
    const int colBase = blockIdx.x * 128;   // d

    float acc[2][8][4] = {};
    gemm_core(sb,
              g_pf  + ((size_t)b * GN + rowBase) * GN, GN,
              g_xth + ((size_t)b * GD + colBase) * GN, GN,
              GN / 32, acc);

    const int l = threadIdx.x & 31;
    const int w = threadIdx.x >> 5;
    const int wm = (w & 3) * 32;
    const int wn = (w >> 2) * 64;
    float* Ob = out + (size_t)b * GN * GD;

#pragma unroll
    for (int mf = 0; mf < 2; mf++) {
        const int r0 = rowBase + wm + mf * 16 + (l >> 2);
        const int r1 = r0 + 8;
#pragma unroll
        for (int nf = 0; nf < 8; nf++) {
            const int c = colBase + wn + nf * 8 + (l & 3) * 2;
            *(float2*)(Ob + (size_t)r0 * GD + c) =
                make_float2(acc[mf][nf][0], acc[mf][nf][1]);
            *(float2*)(Ob + (size_t)r1 * GD + c) =
                make_float2(acc[mf][nf][2], acc[mf][nf][3]);
        }
    }
}

// ---------------------------------------------------------------------------
extern "C" void kernel_launch(void* const* d_in, const int* in_sizes, int n_in,
                              void* d_out, int out_size) {
    const float* X   = (const float*)d_in[0];
    const int*   adj = (const int*)d_in[2];
    float*       out = (float*)d_out;

    static bool attrDone = false;
    if (!attrDone) {
        cudaFuncSetAttribute(gemm1_mma, cudaFuncAttributeMaxDynamicSharedMemorySize, SMEM_GEMM);
        cudaFuncSetAttribute(gemm2_mma, cudaFuncAttributeMaxDynamicSharedMemorySize, SMEM_GEMM);
        attrDone = true;
    }

    convert_split<<<dim3(GD / 32, GN / 32, GB), 256>>>(X);
    gemm1_mma<<<dim3(136, 1, GB), 256, SMEM_GEMM>>>(adj);   // triangular tiles
    softmax_inplace<<<GB * GN, 256>>>();
    gemm2_mma<<<dim3(GD / 128, GN / 128, GB), 256, SMEM_GEMM>>>(out);
}

// round 13
// speedup vs baseline: 2.7682x; 1.1073x over previous
#include <cuda_runtime.h>
#include <cuda_fp16.h>
#include <cstdint>

#define GN 2048
#define GD 512
#define GB 8
#define NEG_H (-60000.0f)   // fp16-representable mask value; exp() underflows to 0

// ---------------- device scratch (no allocs allowed) ----------------
__device__ __half  g_pf[(size_t)GB * GN * GN];       // scores -> probs (fp16, in-place)
__device__ __half  g_xh[(size_t)GB * GN * GD];       // X fp16 [b,n,d]
__device__ __half  g_xth[(size_t)GB * GD * GN];      // X^T fp16 [b,d,n]

// ---------------- helpers ----------------
__device__ __forceinline__ uint32_t smem_u32(const void* p) {
    uint32_t a;
    asm("{ .reg .u64 t; cvta.to.shared.u64 t, %1; cvt.u32.u64 %0, t; }" : "=r"(a) : "l"(p));
    return a;
}

#define CP_ASYNC16(dst, src) \
    asm volatile("cp.async.cg.shared.global [%0], [%1], 16;" :: "r"(dst), "l"(src))
#define CP_COMMIT() asm volatile("cp.async.commit_group;" ::: "memory")
#define CP_WAIT0()  asm volatile("cp.async.wait_group 0;" ::: "memory")

__device__ __forceinline__ void ldsm4(uint32_t* r, uint32_t addr) {
    asm volatile("ldmatrix.sync.aligned.m8n8.x4.shared.b16 {%0,%1,%2,%3}, [%4];"
                 : "=r"(r[0]), "=r"(r[1]), "=r"(r[2]), "=r"(r[3]) : "r"(addr));
}

__device__ __forceinline__ void mma16816(float* c, const uint32_t* a, const uint32_t* b) {
    asm volatile(
        "mma.sync.aligned.m16n8k16.row.col.f32.f16.f16.f32 "
        "{%0,%1,%2,%3}, {%4,%5,%6,%7}, {%8,%9}, {%0,%1,%2,%3};"
        : "+f"(c[0]), "+f"(c[1]), "+f"(c[2]), "+f"(c[3])
        : "r"(a[0]), "r"(a[1]), "r"(a[2]), "r"(a[3]), "r"(b[0]), "r"(b[1]));
}

// ---------------- smem layout ----------------
// K-step 64: per stream tile 128 rows x 64 fp16 = 128 B data/row, stride 144 B
// (16B shift per row -> conflict-free ldmatrix).
#define KSTEP    64
#define ROW_B    144
#define STREAM_B (128 * ROW_B)        // 18432 B
#define NSTAGE   2
#define STAGE_B  (2 * STREAM_B)       // A, B = 36864 B
#define SMEM_GEMM (NSTAGE * STAGE_B)  // 73728 B -> 2 CTAs/SM; fp16 T (33792 B) fits

// Load one stage (k-chunk of 64): two streams A and B. 256 threads.
__device__ __forceinline__ void load_stage2(uint32_t smemStage,
                                            const __half* a, int ldA,
                                            const __half* b, int ldB, int k0) {
    const int t = threadIdx.x;
    const __half* srcs[2] = {a, b};
    const int lds[2] = {ldA, ldB};
#pragma unroll
    for (int st = 0; st < 2; st++) {
#pragma unroll
        for (int rep = 0; rep < 4; rep++) {
            int c   = t + rep * 256;          // 0..1023
            int row = c >> 3;                 // 0..127
            int k8  = c & 7;                  // 16B chunk within 64-elem row
            uint32_t d = smemStage + st * STREAM_B + row * ROW_B + k8 * 16;
            const __half* s = srcs[st] + (size_t)row * lds[st] + k0 + k8 * 8;
            CP_ASYNC16(d, s);
        }
    }
}

// Core: acc[2][8][4] += A(128 x K) * B(128 x K)^T, single fp16 term.
// Warp layout 4(m) x 2(n); warp tile 32x64; 2-stage, K-step 64 (4 substeps).
__device__ __forceinline__ void gemm_core(uint32_t sb,
                                          const __half* a, int ldA,
                                          const __half* b, int ldB,
                                          int ksteps, float acc[2][8][4]) {
    const int l = threadIdx.x & 31;
    const int w = threadIdx.x >> 5;
    const int wm = (w & 3) * 32;
    const int wn = (w >> 2) * 64;

    const int aRow = wm + (l & 15);
    const int aCb  = (l >> 4) * 16;
    const int bRow = wn + (l & 7) + ((l >> 4) & 1) * 8;
    const int bCb  = ((l >> 3) & 1) * 16;

    load_stage2(sb, a, ldA, b, ldB, 0);
    CP_COMMIT();

#pragma unroll 1
    for (int i = 0; i < ksteps; i++) {
        CP_WAIT0();            // stage i complete (only group in flight)
        __syncthreads();       // publish stage i; prove other buffer drained

        if (i + 1 < ksteps) {  // prefetch overlaps the 4-substep compute below
            load_stage2(sb + ((i + 1) & 1) * STAGE_B, a, ldA, b, ldB, (i + 1) * KSTEP);
            CP_COMMIT();
        }

        const uint32_t stg = sb + (i & 1) * STAGE_B;
#pragma unroll
        for (int s = 0; s < 4; s++) {
            uint32_t ah[2][4];
#pragma unroll
            for (int mf = 0; mf < 2; mf++)
                ldsm4(ah[mf], stg + (aRow + mf * 16) * ROW_B + s * 32 + aCb);
            uint32_t bh[4][4];
#pragma unroll
            for (int nq = 0; nq < 4; nq++)
                ldsm4(bh[nq], stg + STREAM_B + (bRow + nq * 16) * ROW_B + s * 32 + bCb);
#pragma unroll
            for (int mf = 0; mf < 2; mf++)
#pragma unroll
                for (int nq = 0; nq < 4; nq++)
#pragma unroll
                    for (int h = 0; h < 2; h++)
                        mma16816(acc[mf][nq * 2 + h], ah[mf], &bh[nq][h * 2]);
        }
    }
}

// ---------------------------------------------------------------------------
// Kernel 0: convert X to fp16, plus transposed copy.
// ---------------------------------------------------------------------------
__global__ __launch_bounds__(256) void convert_split(const float* __restrict__ X) {
    __shared__ float tile[32][33];
    const int b  = blockIdx.z;
    const int d0 = blockIdx.x * 32;
    const int n0 = blockIdx.y * 32;
    const int tx = threadIdx.x & 31;
    const int ty = threadIdx.x >> 5;
    const float* Xb = X + (size_t)b * GN * GD;

#pragma unroll
    for (int k = 0; k < 4; k++) {
        int n = n0 + ty + k * 8;
        float v = Xb[(size_t)n * GD + d0 + tx];
        tile[ty + k * 8][tx] = v;
        g_xh[((size_t)b * GN + n) * GD + d0 + tx] = __float2half(v);
    }
    __syncthreads();
#pragma unroll
    for (int k = 0; k < 4; k++) {
        int d = d0 + ty + k * 8;
        float v = tile[tx][ty + k * 8];
        g_xth[((size_t)b * GD + d) * GN + n0 + tx] = __float2half(v);
    }
}

// ---------------------------------------------------------------------------
// Kernel 1: S = X X^T masked by adj (+self) -> g_pf (fp16).
// SYMMETRIC triangular tiles; single fp16 term.
// ---------------------------------------------------------------------------
__global__ __launch_bounds__(256, 2) void gemm1_mma(const int* __restrict__ adj) {
    extern __shared__ char smem[];
    const uint32_t sb = smem_u32(smem);
    const int b = blockIdx.z;

    int rem = blockIdx.x;
    int R = 0;
    while (rem >= 16 - R) { rem -= 16 - R; R++; }
    const int C = R + rem;
    const int rowBase = R * 128;
    const int colBase = C * 128;

    float acc[2][8][4] = {};
    gemm_core(sb,
              g_xh + ((size_t)b * GN + rowBase) * GD, GD,
              g_xh + ((size_t)b * GN + colBase) * GD, GD,
              GD / KSTEP, acc);

    const int l = threadIdx.x & 31;
    const int w = threadIdx.x >> 5;
    const int wm = (w & 3) * 32;
    const int wn = (w >> 2) * 64;
    const int* adjb = adj + (size_t)b * GN * GN;
    __half* Sb = g_pf + (size_t)b * GN * GN;

    // ---- write block (R, C) as fp16: mask adj[n][m] ----
#pragma unroll
    for (int mf = 0; mf < 2; mf++) {
        const int r0 = rowBase + wm + mf * 16 + (l >> 2);
        const int r1 = r0 + 8;
#pragma unroll
        for (int nf = 0; nf < 8; nf++) {
            const int c = colBase + wn + nf * 8 + (l & 3) * 2;
            int2 a0 = *(const int2*)(adjb + (size_t)r0 * GN + c);
            int2 a1 = *(const int2*)(adjb + (size_t)r1 * GN + c);
            float v00 = (a0.x != 0 || r0 == c)     ? acc[mf][nf][0] : NEG_H;
            float v01 = (a0.y != 0 || r0 == c + 1) ? acc[mf][nf][1] : NEG_H;
            float v10 = (a1.x != 0 || r1 == c)     ? acc[mf][nf][2] : NEG_H;
            float v11 = (a1.y != 0 || r1 == c + 1) ? acc[mf][nf][3] : NEG_H;
            *(__half2*)(Sb + (size_t)r0 * GN + c) = __floats2half2_rn(v00, v01);
            *(__half2*)(Sb + (size_t)r1 * GN + c) = __floats2half2_rn(v10, v11);
        }
    }

    // ---- mirror block (C, R): S[m][n] = acc^T (fp16), mask adj[m][n] ----
    if (C != R) {
        __syncthreads();
        __half* T = (__half*)smem;           // [128][132] fp16 transpose stage
#pragma unroll
        for (int mf = 0; mf < 2; mf++) {
            const int rl0 = wm + mf * 16 + (l >> 2);
            const int rl1 = rl0 + 8;
#pragma unroll
            for (int nf = 0; nf < 8; nf++) {
                const int cl = wn + nf * 8 + (l & 3) * 2;
                T[(cl)     * 132 + rl0] = __float2half(acc[mf][nf][0]);
                T[(cl + 1) * 132 + rl0] = __float2half(acc[mf][nf][1]);
                T[(cl)     * 132 + rl1] = __float2half(acc[mf][nf][2]);
                T[(cl + 1) * 132 + rl1] = __float2half(acc[mf][nf][3]);
            }
        }
        __syncthreads();
#pragma unroll
        for (int mf = 0; mf < 2; mf++) {
            const int ml0 = wm + mf * 16 + (l >> 2);
            const int ml1 = ml0 + 8;
            const int m0 = colBase + ml0;
            const int m1 = colBase + ml1;
#pragma unroll
            for (int nf = 0; nf < 8; nf++) {
                const int nl = wn + nf * 8 + (l & 3) * 2;
                const int nn = rowBase + nl;
                int2 a0 = *(const int2*)(adjb + (size_t)m0 * GN + nn);
                int2 a1 = *(const int2*)(adjb + (size_t)m1 * GN + nn);
                __half2 o0, o1;
                __half negh = __float2half(NEG_H);
                o0.x = (a0.x != 0) ? T[ml0 * 132 + nl]     : negh;
                o0.y = (a0.y != 0) ? T[ml0 * 132 + nl + 1] : negh;
                o1.x = (a1.x != 0) ? T[ml1 * 132 + nl]     : negh;
                o1.y = (a1.y != 0) ? T[ml1 * 132 + nl + 1] : negh;
                *(__half2*)(Sb + (size_t)m0 * GN + nn) = o0;
                *(__half2*)(Sb + (size_t)m1 * GN + nn) = o1;
            }
        }
    }
}

// ---------------------------------------------------------------------------
// Kernel 2: in-place row softmax over fp16 buffer g_pf.
// ---------------------------------------------------------------------------
__device__ __forceinline__ float warpMax(float v) {
#pragma unroll
    for (int o = 16; o > 0; o >>= 1) v = fmaxf(v, __shfl_xor_sync(0xffffffffu, v, o));
    return v;
}
__device__ __forceinline__ float warpSum(float v) {
#pragma unroll
    for (int o = 16; o > 0; o >>= 1) v += __shfl_xor_sync(0xffffffffu, v, o);
    return v;
}

__global__ __launch_bounds__(256) void softmax_inplace() {
    __shared__ float red[8];
    const size_t row = blockIdx.x;
    __half* p = g_pf + row * GN;
    const int tid = threadIdx.x;

    float4 raw = ((const float4*)p)[tid];
    __half2 h[4];
    h[0] = *(__half2*)&raw.x; h[1] = *(__half2*)&raw.y;
    h[2] = *(__half2*)&raw.z; h[3] = *(__half2*)&raw.w;
    float f[8];
#pragma unroll
    for (int i = 0; i < 4; i++) {
        float2 t = __half22float2(h[i]);
        f[i * 2] = t.x; f[i * 2 + 1] = t.y;
    }

    float m = f[0];
#pragma unroll
    for (int i = 1; i < 8; i++) m = fmaxf(m, f[i]);
    m = warpMax(m);
    if ((tid & 31) == 0) red[tid >> 5] = m;
    __syncthreads();
    m = red[0];
#pragma unroll
    for (int i = 1; i < 8; i++) m = fmaxf(m, red[i]);
    __syncthreads();

    float s = 0.f;
#pragma unroll
    for (int i = 0; i < 8; i++) { f[i] = __expf(f[i] - m); s += f[i]; }
    s = warpSum(s);
    if ((tid & 31) == 0) red[tid >> 5] = s;
    __syncthreads();
    s = red[0] + red[1] + red[2] + red[3] + red[4] + red[5] + red[6] + red[7];

    const float inv = 1.0f / s;
#pragma unroll
    for (int i = 0; i < 4; i++)
        h[i] = __floats2half2_rn(f[i * 2] * inv, f[i * 2 + 1] * inv);
    float4 outv;
    outv.x = *(float*)&h[0]; outv.y = *(float*)&h[1];
    outv.z = *(float*)&h[2]; outv.w = *(float*)&h[3];
    ((float4*)p)[tid] = outv;
}

// ---------------------------------------------------------------------------
// Kernel 3: O = P X. A = P fp16, B = X^T fp16. Single MMA term.
// ---------------------------------------------------------------------------
__global__ __launch_bounds__(256, 2) void gemm2_mma(float* __restrict__ out) {
    extern __shared__ char smem[];
    const uint32_t sb = smem_u32(smem);
    const int b = blockIdx.z;
    const int rowBase = blockIdx.y * 128;   // n
    const int colBase = blockIdx.x * 128;   // d

    float acc[2][8][4] = {};
    gemm_core(sb,
              g_pf  + ((size_t)b * GN + rowBase) * GN, GN,
              g_xth + ((size_t)b * GD + colBase) * GN, GN,
              GN / KSTEP, acc);

    const int l = threadIdx.x & 31;
    const int w = threadIdx.x >> 5;
    const int wm = (w & 3) * 32;
    const int wn = (w >> 2) * 64;
    float* Ob = out + (size_t)b * GN * GD;

#pragma unroll
    for (int mf = 0; mf < 2; mf++) {
        const int r0 = rowBase + wm + mf * 16 + (l >> 2);
        const int r1 = r0 + 8;
#pragma unroll
        for (int nf = 0; nf < 8; nf++) {
            const int c = colBase + wn + nf * 8 + (l & 3) * 2;
            *(float2*)(Ob + (size_t)r0 * GD + c) =
                make_float2(acc[mf][nf][0], acc[mf][nf][1]);
            *(float2*)(Ob + (size_t)r1 * GD + c) =
                make_float2(acc[mf][nf][2], acc[mf][nf][3]);
        }
    }
}

// ---------------------------------------------------------------------------
extern "C" void kernel_launch(void* const* d_in, const int* in_sizes, int n_in,
                              void* d_out, int out_size) {
    const float* X   = (const float*)d_in[0];
    const int*   adj = (const int*)d_in[2];
    float*       out = (float*)d_out;

    static bool attrDone = false;
    if (!attrDone) {
        cudaFuncSetAttribute(gemm1_mma, cudaFuncAttributeMaxDynamicSharedMemorySize, SMEM_GEMM);
        cudaFuncSetAttribute(gemm2_mma, cudaFuncAttributeMaxDynamicSharedMemorySize, SMEM_GEMM);
        attrDone = true;
    }

    convert_split<<<dim3(GD / 32, GN / 32, GB), 256>>>(X);
    gemm1_mma<<<dim3(136, 1, GB), 256, SMEM_GEMM>>>(adj);   // triangular tiles
    softmax_inplace<<<GB * GN, 256>>>();
    gemm2_mma<<<dim3(GD / 128, GN / 128, GB), 256, SMEM_GEMM>>>(out);
}

// round 14
// speedup vs baseline: 2.7761x; 1.0028x over previous
#include <cuda_runtime.h>
#include <cuda_fp16.h>
#include <cstdint>

#define GN 2048
#define GD 512
#define GB 8
#define NEG_H (-60000.0f)   // fp16-representable mask value; exp() underflows to 0

// ---------------- device scratch (no allocs allowed) ----------------
__device__ __half  g_pf[(size_t)GB * GN * GN];       // scores -> probs (fp16, in-place)
__device__ __half  g_xh[(size_t)GB * GN * GD];       // X fp16 [b,n,d]
__device__ __half  g_xth[(size_t)GB * GD * GN];      // X^T fp16 [b,d,n]

// ---------------- helpers ----------------
__device__ __forceinline__ uint32_t smem_u32(const void* p) {
    uint32_t a;
    asm("{ .reg .u64 t; cvta.to.shared.u64 t, %1; cvt.u32.u64 %0, t; }" : "=r"(a) : "l"(p));
    return a;
}

#define CP_ASYNC16(dst, src) \
    asm volatile("cp.async.cg.shared.global [%0], [%1], 16;" :: "r"(dst), "l"(src))
#define CP_COMMIT() asm volatile("cp.async.commit_group;" ::: "memory")
#define CP_WAIT0()  asm volatile("cp.async.wait_group 0;" ::: "memory")

__device__ __forceinline__ void ldsm4(uint32_t* r, uint32_t addr) {
    asm volatile("ldmatrix.sync.aligned.m8n8.x4.shared.b16 {%0,%1,%2,%3}, [%4];"
                 : "=r"(r[0]), "=r"(r[1]), "=r"(r[2]), "=r"(r[3]) : "r"(addr));
}

__device__ __forceinline__ void mma16816(float* c, const uint32_t* a, const uint32_t* b) {
    asm volatile(
        "mma.sync.aligned.m16n8k16.row.col.f32.f16.f16.f32 "
        "{%0,%1,%2,%3}, {%4,%5,%6,%7}, {%8,%9}, {%0,%1,%2,%3};"
        : "+f"(c[0]), "+f"(c[1]), "+f"(c[2]), "+f"(c[3])
        : "r"(a[0]), "r"(a[1]), "r"(a[2]), "r"(a[3]), "r"(b[0]), "r"(b[1]));
}

// ---------------- smem layout ----------------
// K-step 64: per stream tile 128 rows x 64 fp16 = 128 B data/row, stride 144 B
// (16B shift per row -> conflict-free ldmatrix).
#define KSTEP    64
#define ROW_B    144
#define STREAM_B (128 * ROW_B)        // 18432 B
#define NSTAGE   2
#define STAGE_B  (2 * STREAM_B)       // A, B = 36864 B
#define SMEM_GEMM (NSTAGE * STAGE_B)  // 73728 B -> 2 CTAs/SM; fp16 T (33792 B) fits

// Load one stage (k-chunk of 64): two streams A and B. 256 threads.
__device__ __forceinline__ void load_stage2(uint32_t smemStage,
                                            const __half* a, int ldA,
                                            const __half* b, int ldB, int k0) {
    const int t = threadIdx.x;
    const __half* srcs[2] = {a, b};
    const int lds[2] = {ldA, ldB};
#pragma unroll
    for (int st = 0; st < 2; st++) {
#pragma unroll
        for (int rep = 0; rep < 4; rep++) {
            int c   = t + rep * 256;          // 0..1023
            int row = c >> 3;                 // 0..127
            int k8  = c & 7;                  // 16B chunk within 64-elem row
            uint32_t d = smemStage + st * STREAM_B + row * ROW_B + k8 * 16;
            const __half* s = srcs[st] + (size_t)row * lds[st] + k0 + k8 * 8;
            CP_ASYNC16(d, s);
        }
    }
}

// Core: acc[2][8][4] += A(128 x K) * B(128 x K)^T, single fp16 term.
// Warp layout 4(m) x 2(n); warp tile 32x64; 2-stage, K-step 64 (4 substeps).
__device__ __forceinline__ void gemm_core(uint32_t sb,
                                          const __half* a, int ldA,
                                          const __half* b, int ldB,
                                          int ksteps, float acc[2][8][4]) {
    const int l = threadIdx.x & 31;
    const int w = threadIdx.x >> 5;
    const int wm = (w & 3) * 32;
    const int wn = (w >> 2) * 64;

    const int aRow = wm + (l & 15);
    const int aCb  = (l >> 4) * 16;
    const int bRow = wn + (l & 7) + ((l >> 4) & 1) * 8;
    const int bCb  = ((l >> 3) & 1) * 16;

    load_stage2(sb, a, ldA, b, ldB, 0);
    CP_COMMIT();

#pragma unroll 1
    for (int i = 0; i < ksteps; i++) {
        CP_WAIT0();            // stage i complete (only group in flight)
        __syncthreads();       // publish stage i; prove other buffer drained

        if (i + 1 < ksteps) {  // prefetch overlaps the 4-substep compute below
            load_stage2(sb + ((i + 1) & 1) * STAGE_B, a, ldA, b, ldB, (i + 1) * KSTEP);
            CP_COMMIT();
        }

        const uint32_t stg = sb + (i & 1) * STAGE_B;
#pragma unroll
        for (int s = 0; s < 4; s++) {
            uint32_t ah[2][4];
#pragma unroll
            for (int mf = 0; mf < 2; mf++)
                ldsm4(ah[mf], stg + (aRow + mf * 16) * ROW_B + s * 32 + aCb);
            uint32_t bh[4][4];
#pragma unroll
            for (int nq = 0; nq < 4; nq++)
                ldsm4(bh[nq], stg + STREAM_B + (bRow + nq * 16) * ROW_B + s * 32 + bCb);
#pragma unroll
            for (int mf = 0; mf < 2; mf++)
#pragma unroll
                for (int nq = 0; nq < 4; nq++)
#pragma unroll
                    for (int h = 0; h < 2; h++)
                        mma16816(acc[mf][nq * 2 + h], ah[mf], &bh[nq][h * 2]);
        }
    }
}

// ---------------------------------------------------------------------------
// Kernel 0: convert X to fp16, plus transposed copy.
// ---------------------------------------------------------------------------
__global__ __launch_bounds__(256) void convert_split(const float* __restrict__ X) {
    __shared__ float tile[32][33];
    const int b  = blockIdx.z;
    const int d0 = blockIdx.x * 32;
    const int n0 = blockIdx.y * 32;
    const int tx = threadIdx.x & 31;
    const int ty = threadIdx.x >> 5;
    const float* Xb = X + (size_t)b * GN * GD;

#pragma unroll
    for (int k = 0; k < 4; k++) {
        int n = n0 + ty + k * 8;
        float v = Xb[(size_t)n * GD + d0 + tx];
        tile[ty + k * 8][tx] = v;
        g_xh[((size_t)b * GN + n) * GD + d0 + tx] = __float2half(v);
    }
    __syncthreads();
#pragma unroll
    for (int k = 0; k < 4; k++) {
        int d = d0 + ty + k * 8;
        float v = tile[tx][ty + k * 8];
        g_xth[((size_t)b * GD + d) * GN + n0 + tx] = __float2half(v);
    }
}

// ---------------------------------------------------------------------------
// Kernel 1: S = X X^T masked by adj (+self) -> g_pf (fp16).
// SYMMETRIC triangular tiles; single fp16 term.
// ---------------------------------------------------------------------------
__global__ __launch_bounds__(256, 2) void gemm1_mma(const int* __restrict__ adj) {
    extern __shared__ char smem[];
    const uint32_t sb = smem_u32(smem);
    const int b = blockIdx.z;

    int rem = blockIdx.x;
    int R = 0;
    while (rem >= 16 - R) { rem -= 16 - R; R++; }
    const int C = R + rem;
    const int rowBase = R * 128;
    const int colBase = C * 128;

    float acc[2][8][4] = {};
    gemm_core(sb,
              g_xh + ((size_t)b * GN + rowBase) * GD, GD,
              g_xh + ((size_t)b * GN + colBase) * GD, GD,
              GD / KSTEP, acc);

    const int l = threadIdx.x & 31;
    const int w = threadIdx.x >> 5;
    const int wm = (w & 3) * 32;
    const int wn = (w >> 2) * 64;
    const int* adjb = adj + (size_t)b * GN * GN;
    __half* Sb = g_pf + (size_t)b * GN * GN;

    // ---- write block (R, C) as fp16: mask adj[n][m] ----
#pragma unroll
    for (int mf = 0; mf < 2; mf++) {
        const int r0 = rowBase + wm + mf * 16 + (l >> 2);
        const int r1 = r0 + 8;
#pragma unroll
        for (int nf = 0; nf < 8; nf++) {
            const int c = colBase + wn + nf * 8 + (l & 3) * 2;
            int2 a0 = *(const int2*)(adjb + (size_t)r0 * GN + c);
            int2 a1 = *(const int2*)(adjb + (size_t)r1 * GN + c);
            float v00 = (a0.x != 0 || r0 == c)     ? acc[mf][nf][0] : NEG_H;
            float v01 = (a0.y != 0 || r0 == c + 1) ? acc[mf][nf][1] : NEG_H;
            float v10 = (a1.x != 0 || r1 == c)     ? acc[mf][nf][2] : NEG_H;
            float v11 = (a1.y != 0 || r1 == c + 1) ? acc[mf][nf][3] : NEG_H;
            *(__half2*)(Sb + (size_t)r0 * GN + c) = __floats2half2_rn(v00, v01);
            *(__half2*)(Sb + (size_t)r1 * GN + c) = __floats2half2_rn(v10, v11);
        }
    }

    // ---- mirror block (C, R): S[m][n] = acc^T (fp16), mask adj[m][n] ----
    if (C != R) {
        __syncthreads();
        __half* T = (__half*)smem;           // [128][132] fp16 transpose stage
#pragma unroll
        for (int mf = 0; mf < 2; mf++) {
            const int rl0 = wm + mf * 16 + (l >> 2);
            const int rl1 = rl0 + 8;
#pragma unroll
            for (int nf = 0; nf < 8; nf++) {
                const int cl = wn + nf * 8 + (l & 3) * 2;
                T[(cl)     * 132 + rl0] = __float2half(acc[mf][nf][0]);
                T[(cl + 1) * 132 + rl0] = __float2half(acc[mf][nf][1]);
                T[(cl)     * 132 + rl1] = __float2half(acc[mf][nf][2]);
                T[(cl + 1) * 132 + rl1] = __float2half(acc[mf][nf][3]);
            }
        }
        __syncthreads();
#pragma unroll
        for (int mf = 0; mf < 2; mf++) {
            const int ml0 = wm + mf * 16 + (l >> 2);
            const int ml1 = ml0 + 8;
            const int m0 = colBase + ml0;
            const int m1 = colBase + ml1;
#pragma unroll
            for (int nf = 0; nf < 8; nf++) {
                const int nl = wn + nf * 8 + (l & 3) * 2;
                const int nn = rowBase + nl;
                int2 a0 = *(const int2*)(adjb + (size_t)m0 * GN + nn);
                int2 a1 = *(const int2*)(adjb + (size_t)m1 * GN + nn);
                __half2 o0, o1;
                __half negh = __float2half(NEG_H);
                o0.x = (a0.x != 0) ? T[ml0 * 132 + nl]     : negh;
                o0.y = (a0.y != 0) ? T[ml0 * 132 + nl + 1] : negh;
                o1.x = (a1.x != 0) ? T[ml1 * 132 + nl]     : negh;
                o1.y = (a1.y != 0) ? T[ml1 * 132 + nl + 1] : negh;
                *(__half2*)(Sb + (size_t)m0 * GN + nn) = o0;
                *(__half2*)(Sb + (size_t)m1 * GN + nn) = o1;
            }
        }
    }
}

// ---------------------------------------------------------------------------
// Kernel 2: in-place row softmax over fp16 buffer g_pf.
// ---------------------------------------------------------------------------
__device__ __forceinline__ float warpMax(float v) {
#pragma unroll
    for (int o = 16; o > 0; o >>= 1) v = fmaxf(v, __shfl_xor_sync(0xffffffffu, v, o));
    return v;
}
__device__ __forceinline__ float warpSum(float v) {
#pragma unroll
    for (int o = 16; o > 0; o >>= 1) v += __shfl_xor_sync(0xffffffffu, v, o);
    return v;
}

__global__ __launch_bounds__(256) void softmax_inplace() {
    __shared__ float red[8];
    const size_t row = blockIdx.x;
    __half* p = g_pf + row * GN;
    const int tid = threadIdx.x;

    float4 raw = ((const float4*)p)[tid];
    __half2 h[4];
    h[0] = *(__half2*)&raw.x; h[1] = *(__half2*)&raw.y;
    h[2] = *(__half2*)&raw.z; h[3] = *(__half2*)&raw.w;
    float f[8];
#pragma unroll
    for (int i = 0; i < 4; i++) {
        float2 t = __half22float2(h[i]);
        f[i * 2] = t.x; f[i * 2 + 1] = t.y;
    }

    float m = f[0];
#pragma unroll
    for (int i = 1; i < 8; i++) m = fmaxf(m, f[i]);
    m = warpMax(m);
    if ((tid & 31) == 0) red[tid >> 5] = m;
    __syncthreads();
    m = red[0];
#pragma unroll
    for (int i = 1; i < 8; i++) m = fmaxf(m, red[i]);
    __syncthreads();

    float s = 0.f;
#pragma unroll
    for (int i = 0; i < 8; i++) { f[i] = __expf(f[i] - m); s += f[i]; }
    s = warpSum(s);
    if ((tid & 31) == 0) red[tid >> 5] = s;
    __syncthreads();
    s = red[0] + red[1] + red[2] + red[3] + red[4] + red[5] + red[6] + red[7];

    const float inv = 1.0f / s;
#pragma unroll
    for (int i = 0; i < 4; i++)
        h[i] = __floats2half2_rn(f[i * 2] * inv, f[i * 2 + 1] * inv);
    float4 outv;
    outv.x = *(float*)&h[0]; outv.y = *(float*)&h[1];
    outv.z = *(float*)&h[2]; outv.w = *(float*)&h[3];
    ((float4*)p)[tid] = outv;
}

// ---------------------------------------------------------------------------
// Kernel 3: O = P X. A = P fp16, B = X^T fp16. Single MMA term.
// ---------------------------------------------------------------------------
__global__ __launch_bounds__(256, 2) void gemm2_mma(float* __restrict__ out) {
    extern __shared__ char smem[];
    const uint32_t sb = smem_u32(smem);
    const int b = blockIdx.z;
    const int rowBase = blockIdx.y * 128;   // n
    const int colBase = blockIdx.x * 128;   // d

    float acc[2][8][4] = {};
    gemm_core(sb,
              g_pf  + ((size_t)b * GN + rowBase) * GN, GN,
              g_xth + ((size_t)b * GD + colBase) * GN, GN,
              GN / KSTEP, acc);

    const int l = threadIdx.x & 31;
    const int w = threadIdx.x >> 5;
    const int wm = (w & 3) * 32;
    const int wn = (w >> 2) * 64;
    float* Ob = out + (size_t)b * GN * GD;

#pragma unroll
    for (int mf = 0; mf < 2; mf++) {
        const int r0 = rowBase + wm + mf * 16 + (l >> 2);
        const int r1 = r0 + 8;
#pragma unroll
        for (int nf = 0; nf < 8; nf++) {
            const int c = colBase + wn + nf * 8 + (l & 3) * 2;
            *(float2*)(Ob + (size_t)r0 * GD + c) =
                make_float2(acc[mf][nf][0], acc[mf][nf][1]);
            *(float2*)(Ob + (size_t)r1 * GD + c) =
                make_float2(acc[mf][nf][2], acc[mf][nf][3]);
        }
    }
}

// ---------------------------------------------------------------------------
extern "C" void kernel_launch(void* const* d_in, const int* in_sizes, int n_in,
                              void* d_out, int out_size) {
    const float* X   = (const float*)d_in[0];
    const int*   adj = (const int*)d_in[2];
    float*       out = (float*)d_out;

    static bool attrDone = false;
    if (!attrDone) {
        cudaFuncSetAttribute(gemm1_mma, cudaFuncAttributeMaxDynamicSharedMemorySize, SMEM_GEMM);
        cudaFuncSetAttribute(gemm2_mma, cudaFuncAttributeMaxDynamicSharedMemorySize, SMEM_GEMM);
        attrDone = true;
    }

    convert_split<<<dim3(GD / 32, GN / 32, GB), 256>>>(X);
    gemm1_mma<<<dim3(136, 1, GB), 256, SMEM_GEMM>>>(adj);   // triangular tiles
    softmax_inplace<<<GB * GN, 256>>>();
    gemm2_mma<<<dim3(GD / 128, GN / 128, GB), 256, SMEM_GEMM>>>(out);
}

// round 15
// speedup vs baseline: 2.8696x; 1.0337x over previous
#include <cuda_runtime.h>
#include <cuda_fp16.h>
#include <cstdint>

#define GN 2048
#define GD 512
#define GB 8
#define NEG_H (-60000.0f)   // fp16-representable mask value; exp() underflows to 0

// ---------------- device scratch (no allocs allowed) ----------------
__device__ __half  g_pf[(size_t)GB * GN * GN];       // scores -> probs (fp16, in-place)
__device__ __half  g_xh[(size_t)GB * GN * GD];       // X fp16 [b,n,d]
__device__ __half  g_xth[(size_t)GB * GD * GN];      // X^T fp16 [b,d,n]

// ---------------- helpers ----------------
__device__ __forceinline__ uint32_t smem_u32(const void* p) {
    uint32_t a;
    asm("{ .reg .u64 t; cvta.to.shared.u64 t, %1; cvt.u32.u64 %0, t; }" : "=r"(a) : "l"(p));
    return a;
}

#define CP_ASYNC16(dst, src) \
    asm volatile("cp.async.cg.shared.global [%0], [%1], 16;" :: "r"(dst), "l"(src))
#define CP_COMMIT() asm volatile("cp.async.commit_group;" ::: "memory")
#define CP_WAIT0()  asm volatile("cp.async.wait_group 0;" ::: "memory")

__device__ __forceinline__ void ldsm4(uint32_t* r, uint32_t addr) {
    asm volatile("ldmatrix.sync.aligned.m8n8.x4.shared.b16 {%0,%1,%2,%3}, [%4];"
                 : "=r"(r[0]), "=r"(r[1]), "=r"(r[2]), "=r"(r[3]) : "r"(addr));
}

__device__ __forceinline__ void mma16816(float* c, const uint32_t* a, const uint32_t* b) {
    asm volatile(
        "mma.sync.aligned.m16n8k16.row.col.f32.f16.f16.f32 "
        "{%0,%1,%2,%3}, {%4,%5,%6,%7}, {%8,%9}, {%0,%1,%2,%3};"
        : "+f"(c[0]), "+f"(c[1]), "+f"(c[2]), "+f"(c[3])
        : "r"(a[0]), "r"(a[1]), "r"(a[2]), "r"(a[3]), "r"(b[0]), "r"(b[1]));
}

// ---------------- smem layout ----------------
// K-step 64: per stream tile 128 rows x 64 fp16 = 128 B data/row, stride 144 B.
#define KSTEP    64
#define ROW_B    144
#define STREAM_B (128 * ROW_B)        // 18432 B
#define NSTAGE   2
#define STAGE_B  (2 * STREAM_B)       // A, B = 36864 B
#define SMEM_GEMM (NSTAGE * STAGE_B)  // 73728 B -> 2 CTAs/SM; fp16 T (33792 B) fits

// Load one stage (k-chunk of 64): two streams A and B. 256 threads.
__device__ __forceinline__ void load_stage2(uint32_t smemStage,
                                            const __half* a, int ldA,
                                            const __half* b, int ldB, int k0) {
    const int t = threadIdx.x;
    const __half* srcs[2] = {a, b};
    const int lds[2] = {ldA, ldB};
#pragma unroll
    for (int st = 0; st < 2; st++) {
#pragma unroll
        for (int rep = 0; rep < 4; rep++) {
            int c   = t + rep * 256;          // 0..1023
            int row = c >> 3;                 // 0..127
            int k8  = c & 7;                  // 16B chunk within 64-elem row
            uint32_t d = smemStage + st * STREAM_B + row * ROW_B + k8 * 16;
            const __half* s = srcs[st] + (size_t)row * lds[st] + k0 + k8 * 8;
            CP_ASYNC16(d, s);
        }
    }
}

// Core: acc[2][8][4] += A(128 x K) * B(128 x K)^T, single fp16 term.
__device__ __forceinline__ void gemm_core(uint32_t sb,
                                          const __half* a, int ldA,
                                          const __half* b, int ldB,
                                          int ksteps, float acc[2][8][4]) {
    const int l = threadIdx.x & 31;
    const int w = threadIdx.x >> 5;
    const int wm = (w & 3) * 32;
    const int wn = (w >> 2) * 64;

    const int aRow = wm + (l & 15);
    const int aCb  = (l >> 4) * 16;
    const int bRow = wn + (l & 7) + ((l >> 4) & 1) * 8;
    const int bCb  = ((l >> 3) & 1) * 16;

    load_stage2(sb, a, ldA, b, ldB, 0);
    CP_COMMIT();

#pragma unroll 1
    for (int i = 0; i < ksteps; i++) {
        CP_WAIT0();
        __syncthreads();

        if (i + 1 < ksteps) {
            load_stage2(sb + ((i + 1) & 1) * STAGE_B, a, ldA, b, ldB, (i + 1) * KSTEP);
            CP_COMMIT();
        }

        const uint32_t stg = sb + (i & 1) * STAGE_B;
#pragma unroll
        for (int s = 0; s < 4; s++) {
            uint32_t ah[2][4];
#pragma unroll
            for (int mf = 0; mf < 2; mf++)
                ldsm4(ah[mf], stg + (aRow + mf * 16) * ROW_B + s * 32 + aCb);
            uint32_t bh[4][4];
#pragma unroll
            for (int nq = 0; nq < 4; nq++)
                ldsm4(bh[nq], stg + STREAM_B + (bRow + nq * 16) * ROW_B + s * 32 + bCb);
#pragma unroll
            for (int mf = 0; mf < 2; mf++)
#pragma unroll
                for (int nq = 0; nq < 4; nq++)
#pragma unroll
                    for (int h = 0; h < 2; h++)
                        mma16816(acc[mf][nq * 2 + h], ah[mf], &bh[nq][h * 2]);
        }
    }
}

// ---------------------------------------------------------------------------
// Kernel 0: convert X to fp16, plus transposed copy.
// ---------------------------------------------------------------------------
__global__ __launch_bounds__(256) void convert_split(const float* __restrict__ X) {
    __shared__ float tile[32][33];
    const int b  = blockIdx.z;
    const int d0 = blockIdx.x * 32;
    const int n0 = blockIdx.y * 32;
    const int tx = threadIdx.x & 31;
    const int ty = threadIdx.x >> 5;
    const float* Xb = X + (size_t)b * GN * GD;

#pragma unroll
    for (int k = 0; k < 4; k++) {
        int n = n0 + ty + k * 8;
        float v = Xb[(size_t)n * GD + d0 + tx];
        tile[ty + k * 8][tx] = v;
        g_xh[((size_t)b * GN + n) * GD + d0 + tx] = __float2half(v);
    }
    __syncthreads();
#pragma unroll
    for (int k = 0; k < 4; k++) {
        int d = d0 + ty + k * 8;
        float v = tile[tx][ty + k * 8];
        g_xth[((size_t)b * GD + d) * GN + n0 + tx] = __float2half(v);
    }
}

// ---------------------------------------------------------------------------
// Kernel 1: S = X X^T masked by adj (+self) -> g_pf (fp16).
// SYMMETRIC triangular tiles; single fp16 term.
// ---------------------------------------------------------------------------
__global__ __launch_bounds__(256, 2) void gemm1_mma(const int* __restrict__ adj) {
    extern __shared__ char smem[];
    const uint32_t sb = smem_u32(smem);
    const int b = blockIdx.z;

    int rem = blockIdx.x;
    int R = 0;
    while (rem >= 16 - R) { rem -= 16 - R; R++; }
    const int C = R + rem;
    const int rowBase = R * 128;
    const int colBase = C * 128;

    float acc[2][8][4] = {};
    gemm_core(sb,
              g_xh + ((size_t)b * GN + rowBase) * GD, GD,
              g_xh + ((size_t)b * GN + colBase) * GD, GD,
              GD / KSTEP, acc);

    const int l = threadIdx.x & 31;
    const int w = threadIdx.x >> 5;
    const int wm = (w & 3) * 32;
    const int wn = (w >> 2) * 64;
    const int* adjb = adj + (size_t)b * GN * GN;
    __half* Sb = g_pf + (size_t)b * GN * GN;

    // ---- write block (R, C) as fp16: mask adj[n][m] ----
#pragma unroll
    for (int mf = 0; mf < 2; mf++) {
        const int r0 = rowBase + wm + mf * 16 + (l >> 2);
        const int r1 = r0 + 8;
#pragma unroll
        for (int nf = 0; nf < 8; nf++) {
            const int c = colBase + wn + nf * 8 + (l & 3) * 2;
            int2 a0 = *(const int2*)(adjb + (size_t)r0 * GN + c);
            int2 a1 = *(const int2*)(adjb + (size_t)r1 * GN + c);
            float v00 = (a0.x != 0 || r0 == c)     ? acc[mf][nf][0] : NEG_H;
            float v01 = (a0.y != 0 || r0 == c + 1) ? acc[mf][nf][1] : NEG_H;
            float v10 = (a1.x != 0 || r1 == c)     ? acc[mf][nf][2] : NEG_H;
            float v11 = (a1.y != 0 || r1 == c + 1) ? acc[mf][nf][3] : NEG_H;
            *(__half2*)(Sb + (size_t)r0 * GN + c) = __floats2half2_rn(v00, v01);
            *(__half2*)(Sb + (size_t)r1 * GN + c) = __floats2half2_rn(v10, v11);
        }
    }

    // ---- mirror block (C, R): S[m][n] = acc^T (fp16), mask adj[m][n] ----
    if (C != R) {
        __syncthreads();
        __half* T = (__half*)smem;           // [128][132] fp16 transpose stage
#pragma unroll
        for (int mf = 0; mf < 2; mf++) {
            const int rl0 = wm + mf * 16 + (l >> 2);
            const int rl1 = rl0 + 8;
#pragma unroll
            for (int nf = 0; nf < 8; nf++) {
                const int cl = wn + nf * 8 + (l & 3) * 2;
                T[(cl)     * 132 + rl0] = __float2half(acc[mf][nf][0]);
                T[(cl + 1) * 132 + rl0] = __float2half(acc[mf][nf][1]);
                T[(cl)     * 132 + rl1] = __float2half(acc[mf][nf][2]);
                T[(cl + 1) * 132 + rl1] = __float2half(acc[mf][nf][3]);
            }
        }
        __syncthreads();
#pragma unroll
        for (int mf = 0; mf < 2; mf++) {
            const int ml0 = wm + mf * 16 + (l >> 2);
            const int ml1 = ml0 + 8;
            const int m0 = colBase + ml0;
            const int m1 = colBase + ml1;
#pragma unroll
            for (int nf = 0; nf < 8; nf++) {
                const int nl = wn + nf * 8 + (l & 3) * 2;
                const int nn = rowBase + nl;
                int2 a0 = *(const int2*)(adjb + (size_t)m0 * GN + nn);
                int2 a1 = *(const int2*)(adjb + (size_t)m1 * GN + nn);
                __half2 o0, o1;
                __half negh = __float2half(NEG_H);
                o0.x = (a0.x != 0) ? T[ml0 * 132 + nl]     : negh;
                o0.y = (a0.y != 0) ? T[ml0 * 132 + nl + 1] : negh;
                o1.x = (a1.x != 0) ? T[ml1 * 132 + nl]     : negh;
                o1.y = (a1.y != 0) ? T[ml1 * 132 + nl + 1] : negh;
                *(__half2*)(Sb + (size_t)m0 * GN + nn) = o0;
                *(__half2*)(Sb + (size_t)m1 * GN + nn) = o1;
            }
        }
    }
}

// ---------------------------------------------------------------------------
// Kernel 2: warp-per-row in-place softmax over fp16 buffer g_pf.
// 8 warps/CTA = 8 rows/CTA; no __syncthreads; 8 x 16B loads per lane (MLP=8).
// ---------------------------------------------------------------------------
__global__ __launch_bounds__(256) void softmax_warp() {
    const int l = threadIdx.x & 31;
    const int w = threadIdx.x >> 5;
    const size_t row = (size_t)blockIdx.x * 8 + w;
    __half* p = g_pf + row * GN;

    // load full row: 8 x uint4 per lane, lane-contiguous 16B chunks
    uint4 v[8];
#pragma unroll
    for (int j = 0; j < 8; j++)
        v[j] = ((const uint4*)p)[j * 32 + l];

    // max over 64 halfs (via half2 max, then to float)
    __half2 m2 = *(__half2*)&v[0].x;
#pragma unroll
    for (int j = 0; j < 8; j++) {
        const uint32_t* u = (const uint32_t*)&v[j];
#pragma unroll
        for (int q = 0; q < 4; q++) {
            __half2 h = *(__half2*)&u[q];
            m2 = __hmax2(m2, h);
        }
    }
    float m = fmaxf(__low2float(m2), __high2float(m2));
#pragma unroll
    for (int o = 16; o > 0; o >>= 1) m = fmaxf(m, __shfl_xor_sync(0xffffffffu, m, o));

    // exp + sum (fp32), write back into v as exp'd halfs (unnormalized)
    float s = 0.f;
#pragma unroll
    for (int j = 0; j < 8; j++) {
        uint32_t* u = (uint32_t*)&v[j];
#pragma unroll
        for (int q = 0; q < 4; q++) {
            float2 t = __half22float2(*(__half2*)&u[q]);
            t.x = __expf(t.x - m);
            t.y = __expf(t.y - m);
            s += t.x + t.y;
            *(__half2*)&u[q] = __floats2half2_rn(t.x, t.y);
        }
    }
#pragma unroll
    for (int o = 16; o > 0; o >>= 1) s += __shfl_xor_sync(0xffffffffu, s, o);

    const float inv = 1.0f / s;
    __half2 inv2 = __float2half2_rn(inv);
#pragma unroll
    for (int j = 0; j < 8; j++) {
        uint32_t* u = (uint32_t*)&v[j];
#pragma unroll
        for (int q = 0; q < 4; q++)
            *(__half2*)&u[q] = __hmul2(*(__half2*)&u[q], inv2);
        ((uint4*)p)[j * 32 + l] = v[j];
    }
}

// ---------------------------------------------------------------------------
// Kernel 3: O = P X. A = P fp16, B = X^T fp16. Single MMA term.
// ---------------------------------------------------------------------------
__global__ __launch_bounds__(256, 2) void gemm2_mma(float* __restrict__ out) {
    extern __shared__ char smem[];
    const uint32_t sb = smem_u32(smem);
    const int b = blockIdx.z;
    const int rowBase = blockIdx.y * 128;   // n
    const int colBase = blockIdx.x * 128;   // d

    float acc[2][8][4] = {};
    gemm_core(sb,
              g_pf  + ((size_t)b * GN + rowBase) * GN, GN,
              g_xth + ((size_t)b * GD + colBase) * GN, GN,
              GN / KSTEP, acc);

    const int l = threadIdx.x & 31;
    const int w = threadIdx.x >> 5;
    const int wm = (w & 3) * 32;
    const int wn = (w >> 2) * 64;
    float* Ob = out + (size_t)b * GN * GD;

#pragma unroll
    for (int mf = 0; mf < 2; mf++) {
        const int r0 = rowBase + wm + mf * 16 + (l >> 2);
        const int r1 = r0 + 8;
#pragma unroll
        for (int nf = 0; nf < 8; nf++) {
            const int c = colBase + wn + nf * 8 + (l & 3) * 2;
            *(float2*)(Ob + (size_t)r0 * GD + c) =
                make_float2(acc[mf][nf][0], acc[mf][nf][1]);
            *(float2*)(Ob + (size_t)r1 * GD + c) =
                make_float2(acc[mf][nf][2], acc[mf][nf][3]);
        }
    }
}

// ---------------------------------------------------------------------------
extern "C" void kernel_launch(void* const* d_in, const int* in_sizes, int n_in,
                              void* d_out, int out_size) {
    const float* X   = (const float*)d_in[0];
    const int*   adj = (const int*)d_in[2];
    float*       out = (float*)d_out;

    static bool attrDone = false;
    if (!attrDone) {
        cudaFuncSetAttribute(gemm1_mma, cudaFuncAttributeMaxDynamicSharedMemorySize, SMEM_GEMM);
        cudaFuncSetAttribute(gemm2_mma, cudaFuncAttributeMaxDynamicSharedMemorySize, SMEM_GEMM);
        attrDone = true;
    }

    convert_split<<<dim3(GD / 32, GN / 32, GB), 256>>>(X);
    gemm1_mma<<<dim3(136, 1, GB), 256, SMEM_GEMM>>>(adj);   // triangular tiles
    softmax_warp<<<GB * GN / 8, 256>>>();
    gemm2_mma<<<dim3(GD / 128, GN / 128, GB), 256, SMEM_GEMM>>>(out);
}